// round 8
// baseline (speedup 1.0000x reference)
#include <cuda_runtime.h>
#include <cuda_bf16.h>
#include <cstdint>
#include <math.h>

#define NB 2
#define NS 2048
#define ND 2048
#define NH 16
#define HD 128
#define NM (NB*NS)   // 4096 rows

// ---- scratch (static device arrays; no allocation allowed) ----
__device__ float g_q[NM*ND];                     // fp32 Q proj / attention O (reused)
__device__ float g_k[NM*ND];                     // fp32 K proj
__device__ int8_t g_wh8[4ll*ND*ND];              // W^T hi int8, [N][K] K-major
__device__ int8_t g_wl8[4ll*ND*ND];              // W^T lo int8
__device__ float  g_wmax[4*ND];                  // per-N-row absmax of W^T
__device__ int8_t g_ah8[(long long)NM*ND];       // A hi int8 (reused q/k/v/o)
__device__ int8_t g_al8[(long long)NM*ND];       // A lo int8
__device__ float  g_amax[NM];                    // per-row absmax of A
__device__ __nv_bfloat16 g_qh[(long long)NM*ND]; // roped Q hi (scaled)
__device__ __nv_bfloat16 g_ql[(long long)NM*ND];
__device__ __nv_bfloat16 g_kh[(long long)NM*ND]; // roped K hi
__device__ __nv_bfloat16 g_kl[(long long)NM*ND];
__device__ __nv_bfloat16 g_vh[(long long)NM*ND]; // V proj hi
__device__ __nv_bfloat16 g_vl[(long long)NM*ND];

__device__ __forceinline__ uint32_t smem_u32(const void* p) {
    uint32_t a;
    asm("{ .reg .u64 t; cvta.to.shared.u64 t, %1; cvt.u32.u64 %0, t; }"
        : "=r"(a) : "l"(p));
    return a;
}

// ---- base-target tensor core primitives (sm_80-class, valid on compute_103) ----
#define LDSM4(r, addr) \
    asm volatile("ldmatrix.sync.aligned.m8n8.x4.shared.b16 {%0,%1,%2,%3}, [%4];" \
        : "=r"((r)[0]), "=r"((r)[1]), "=r"((r)[2]), "=r"((r)[3]) : "r"(addr))

#define LDSM4T(r, addr) \
    asm volatile("ldmatrix.sync.aligned.m8n8.x4.trans.shared.b16 {%0,%1,%2,%3}, [%4];" \
        : "=r"((r)[0]), "=r"((r)[1]), "=r"((r)[2]), "=r"((r)[3]) : "r"(addr))

#define MMA16816(d, a, b) \
    asm volatile("mma.sync.aligned.m16n8k16.row.col.f32.bf16.bf16.f32 " \
        "{%0,%1,%2,%3}, {%4,%5,%6,%7}, {%8,%9}, {%0,%1,%2,%3};" \
        : "+f"((d)[0]), "+f"((d)[1]), "+f"((d)[2]), "+f"((d)[3]) \
        : "r"((a)[0]), "r"((a)[1]), "r"((a)[2]), "r"((a)[3]), \
          "r"((b)[0]), "r"((b)[1]))

#define IMMA16832(d, a, b) \
    asm volatile("mma.sync.aligned.m16n8k32.row.col.s32.s8.s8.s32 " \
        "{%0,%1,%2,%3}, {%4,%5,%6,%7}, {%8,%9}, {%0,%1,%2,%3};" \
        : "+r"((d)[0]), "+r"((d)[1]), "+r"((d)[2]), "+r"((d)[3]) \
        : "r"((a)[0]), "r"((a)[1]), "r"((a)[2]), "r"((a)[3]), \
          "r"((b)[0]), "r"((b)[1]))

#define CP_ASYNC16(dst, src) \
    asm volatile("cp.async.cg.shared.global [%0], [%1], 16;" \
                 :: "r"(dst), "l"(src) : "memory")
#define CP_COMMIT()  asm volatile("cp.async.commit_group;" ::: "memory")
#define CP_WAIT1()   asm volatile("cp.async.wait_group 1;" ::: "memory")
#define CP_WAIT0()   asm volatile("cp.async.wait_group 0;" ::: "memory")

__device__ __forceinline__ uint32_t bf16x2_pack(float lo, float hi) {
    __nv_bfloat162 v = __floats2bfloat162_rn(lo, hi);
    return *reinterpret_cast<uint32_t*>(&v);
}

__device__ __forceinline__ int pk4(int a, int b, int c, int d) {
    return (a & 255) | ((b & 255) << 8) | ((c & 255) << 16) | ((d & 255) << 24);
}

// ============================================================================
// quant_a: fp32 row [ND] -> int8 2-limb (h,l) + per-row absmax. Block per row.
// q = round(x * 16256/rowmax); h = (q+64)>>7; l = q - 128h  (|l|<=64)
// ============================================================================
__global__ void quant_a_kernel(const float* __restrict__ X,
                               int8_t* __restrict__ h8, int8_t* __restrict__ l8,
                               float* __restrict__ amax)
{
    __shared__ float red[256];
    const int tid = threadIdx.x;
    const long long row = blockIdx.x;
    const float* xr = X + row * ND;
    float v[8];
    *(float4*)&v[0] = ((const float4*)xr)[tid*2];
    *(float4*)&v[4] = ((const float4*)xr)[tid*2+1];
    float m = 0.f;
#pragma unroll
    for (int j = 0; j < 8; j++) m = fmaxf(m, fabsf(v[j]));
    red[tid] = m; __syncthreads();
    for (int o = 128; o > 0; o >>= 1) {
        if (tid < o) red[tid] = fmaxf(red[tid], red[tid + o]);
        __syncthreads();
    }
    const float rm = red[0];
    if (tid == 0) amax[row] = rm;
    const float inv = rm > 0.f ? 16256.0f / rm : 0.f;
    int hq[8], lq[8];
#pragma unroll
    for (int j = 0; j < 8; j++) {
        int iq = __float2int_rn(v[j] * inv);
        hq[j] = (iq + 64) >> 7;
        lq[j] = iq - (hq[j] << 7);
    }
    ((int2*)(h8 + row * ND))[tid] = make_int2(pk4(hq[0],hq[1],hq[2],hq[3]),
                                              pk4(hq[4],hq[5],hq[6],hq[7]));
    ((int2*)(l8 + row * ND))[tid] = make_int2(pk4(lq[0],lq[1],lq[2],lq[3]),
                                              pk4(lq[4],lq[5],lq[6],lq[7]));
}

// ============================================================================
// wmax: per-column absmax of W [K][N] (= per-row of W^T). 32 n per block.
// ============================================================================
__global__ void wmax_kernel(const float* __restrict__ W, float* __restrict__ nmax)
{
    __shared__ float red[256];
    const int tid = threadIdx.x;
    const int n = blockIdx.x * 32 + (tid & 31);
    float m = 0.f;
    for (int k = tid >> 5; k < ND; k += 8)
        m = fmaxf(m, fabsf(W[(long long)k * ND + n]));
    red[tid] = m; __syncthreads();
    for (int o = 128; o >= 32; o >>= 1) {
        if (tid < o) red[tid] = fmaxf(red[tid], red[tid + o]);
        __syncthreads();
    }
    if (tid < 32) nmax[blockIdx.x * 32 + tid] = red[tid];
}

// ============================================================================
// quant_w: W[K][N] fp32 -> W^T[N][K] int8 2-limb using per-n absmax.
// ============================================================================
__global__ void quant_w_kernel(const float* __restrict__ W,
                               const float* __restrict__ nmax,
                               int8_t* __restrict__ h8, int8_t* __restrict__ l8)
{
    __shared__ float t[32][33];
    int n0 = blockIdx.x * 32, k0 = blockIdx.y * 32;
    int tx = threadIdx.x, ty = threadIdx.y;
    for (int r = ty; r < 32; r += 8)
        t[r][tx] = W[(long long)(k0 + r) * ND + n0 + tx];
    __syncthreads();
    for (int r = ty; r < 32; r += 8) {
        float rm = nmax[n0 + r];
        float inv = rm > 0.f ? 16256.0f / rm : 0.f;
        int iq = __float2int_rn(t[tx][r] * inv);
        int hq = (iq + 64) >> 7;
        long long o = (long long)(n0 + r) * ND + k0 + tx;
        h8[o] = (int8_t)hq;
        l8[o] = (int8_t)(iq - (hq << 7));
    }
}

// ============================================================================
// int8 2-limb GEMM on mma.sync IMMA: C = A@B^T scaled + bias
// acc1 = sum h_a h_b, acc2 = sum (h_a l_b + l_a h_b), both exact int32 over K.
// C = sA*sB/127^2 * (acc1 + acc2/128) + bias.
// CTA 128x128, 8 warps (warp tile 64x32), K-chunk 64 int8, double buffer.
// smem rows padded 64B payload -> 80B stride (conflict-free ldmatrix).
// ============================================================================
#define GI_STAGE 40960                    // 4 matrices * 128 rows * 80B
#define GI_SMEM  (2*GI_STAGE)             // 81920

__global__ __launch_bounds__(256)
void gemm_imma_kernel(const int8_t* __restrict__ Ah, const int8_t* __restrict__ Al,
                      const int8_t* __restrict__ Bh, const int8_t* __restrict__ Bl,
                      const float* __restrict__ sA, const float* __restrict__ sB,
                      const float* __restrict__ bias,
                      float* __restrict__ C,
                      __nv_bfloat16* __restrict__ Chi,
                      __nv_bfloat16* __restrict__ Clo)
{
    extern __shared__ char dsm[];
    const uint32_t sb = smem_u32(dsm);
    const int tid  = threadIdx.x;
    const int lane = tid & 31, wid = tid >> 5;
    const int wm = wid & 1, wn = wid >> 1;      // warp tile: m 64, n 32
    const int m0 = blockIdx.y * 128, n0 = blockIdx.x * 128;

    const int lrow = tid >> 1;
    const int lb   = (tid & 1) * 32;
    const int8_t* gsrc[4];
    gsrc[0] = Ah + (long long)(m0 + lrow) * ND + lb;
    gsrc[1] = Al + (long long)(m0 + lrow) * ND + lb;
    gsrc[2] = Bh + (long long)(n0 + lrow) * ND + lb;
    gsrc[3] = Bl + (long long)(n0 + lrow) * ND + lb;
    const uint32_t sdst0 = sb + lrow * 80 + lb;

    int acc1[4][4][4], acc2[4][4][4];
#pragma unroll
    for (int i = 0; i < 4; i++)
#pragma unroll
        for (int j = 0; j < 4; j++)
#pragma unroll
            for (int c = 0; c < 4; c++) { acc1[i][j][c] = 0; acc2[i][j][c] = 0; }

#define GI_ISSUE(ch, stage) do { \
        uint32_t s0 = sdst0 + (stage) * GI_STAGE; \
        _Pragma("unroll") \
        for (int m = 0; m < 4; m++) { \
            const int8_t* g = gsrc[m] + (ch) * 64; \
            uint32_t d = s0 + m * 10240; \
            CP_ASYNC16(d, g); \
            CP_ASYNC16(d + 16, g + 16); \
        } \
        CP_COMMIT(); \
    } while (0)

    GI_ISSUE(0, 0);
    GI_ISSUE(1, 1);

    for (int ch = 0; ch < 32; ch++) {
        const int st = ch & 1;
        CP_WAIT1();
        __syncthreads();
        const uint32_t abase = sb + st * GI_STAGE + (wm * 64) * 80
                             + (lane & 15) * 80 + (lane >> 4) * 16;
        const uint32_t bbase = sb + st * GI_STAGE + 20480 + (wn * 32) * 80
                             + (lane & 15) * 80 + (lane >> 4) * 16;
#pragma unroll
        for (int kk = 0; kk < 2; kk++) {        // two k32 steps per 64B chunk
            uint32_t bh[4][2], bl[4][2];
#pragma unroll
            for (int np = 0; np < 2; np++) {
                uint32_t addr = bbase + np * 1280 + kk * 32;
                uint32_t r[4], s[4];
                LDSM4(r, addr);
                LDSM4(s, addr + 10240);
                bh[np*2+0][0] = r[0]; bh[np*2+0][1] = r[2];
                bh[np*2+1][0] = r[1]; bh[np*2+1][1] = r[3];
                bl[np*2+0][0] = s[0]; bl[np*2+0][1] = s[2];
                bl[np*2+1][0] = s[1]; bl[np*2+1][1] = s[3];
            }
#pragma unroll
            for (int mt = 0; mt < 4; mt++) {
                uint32_t ah[4], al[4];
                uint32_t addr = abase + mt * 1280 + kk * 32;
                LDSM4(ah, addr);
                LDSM4(al, addr + 10240);
#pragma unroll
                for (int nt = 0; nt < 4; nt++) {
                    IMMA16832(acc1[mt][nt], ah, bh[nt]);
                    IMMA16832(acc2[mt][nt], ah, bl[nt]);
                    IMMA16832(acc2[mt][nt], al, bh[nt]);
                }
            }
        }
        __syncthreads();
        if (ch + 2 < 32) GI_ISSUE(ch + 2, st);
        else CP_COMMIT();          // keep group-count invariant for WAIT1
    }

    // ---- epilogue ----
    const float K2 = 1.0f / 16129.0f;    // 1/127^2
    const int r0 = m0 + wm * 64 + (lane >> 2);
    const int c0 = n0 + wn * 32 + (lane & 3) * 2;
#pragma unroll
    for (int nt = 0; nt < 4; nt++) {
        const int c = c0 + nt * 8;
        const float sb0 = sB[c] * K2, sb1 = sB[c + 1] * K2;
        const float b0 = bias[c], b1 = bias[c + 1];
#pragma unroll
        for (int mt = 0; mt < 4; mt++) {
            const int r = r0 + mt * 16;
            const float sa0 = sA[r], sa1 = sA[r + 8];
            float f0 = (float)acc1[mt][nt][0] + (float)acc2[mt][nt][0] * 0.0078125f;
            float f1 = (float)acc1[mt][nt][1] + (float)acc2[mt][nt][1] * 0.0078125f;
            float f2 = (float)acc1[mt][nt][2] + (float)acc2[mt][nt][2] * 0.0078125f;
            float f3 = (float)acc1[mt][nt][3] + (float)acc2[mt][nt][3] * 0.0078125f;
            float v00 = sa0 * sb0 * f0 + b0, v01 = sa0 * sb1 * f1 + b1;
            float v10 = sa1 * sb0 * f2 + b0, v11 = sa1 * sb1 * f3 + b1;
            if (C) {
                *(float2*)&C[(long long)r * ND + c]       = make_float2(v00, v01);
                *(float2*)&C[(long long)(r + 8) * ND + c] = make_float2(v10, v11);
            }
            if (Chi) {
                uint32_t h0 = bf16x2_pack(v00, v01);
                uint32_t h1 = bf16x2_pack(v10, v11);
                float h00 = __uint_as_float(h0 << 16), h01 = __uint_as_float(h0 & 0xFFFF0000u);
                float h10 = __uint_as_float(h1 << 16), h11 = __uint_as_float(h1 & 0xFFFF0000u);
                *(uint32_t*)&Chi[(long long)r * ND + c]       = h0;
                *(uint32_t*)&Chi[(long long)(r + 8) * ND + c] = h1;
                *(uint32_t*)&Clo[(long long)r * ND + c]       = bf16x2_pack(v00 - h00, v01 - h01);
                *(uint32_t*)&Clo[(long long)(r + 8) * ND + c] = bf16x2_pack(v10 - h10, v11 - h11);
            }
        }
    }
#undef GI_ISSUE
}

// ============================================================================
// RoPE + split: read fp32 proj, rotate, scale, write bf16 hi/lo
// ============================================================================
__global__ void rope_split_kernel(const float* __restrict__ X,
                                  __nv_bfloat16* __restrict__ hi,
                                  __nv_bfloat16* __restrict__ lo,
                                  float scale)
{
    int idx = blockIdx.x * blockDim.x + threadIdx.x;  // NM * NH * 64
    int i   = idx & 63;
    int h   = (idx >> 6) & (NH - 1);
    int row = idx >> 10;
    int s   = row & (NS - 1);
    float invf = powf(10000.0f, -(float)i / 64.0f);
    float ang = (float)s * invf;
    float sn, cs;
    sincosf(ang, &sn, &cs);
    long long off = (long long)row * ND + h * HD + i;
    float x1 = X[off], x2 = X[off + 64];
    float o1 = (x1 * cs - x2 * sn) * scale;
    float o2 = (x2 * cs + x1 * sn) * scale;
    __nv_bfloat16 h1 = __float2bfloat16(o1);
    __nv_bfloat16 h2 = __float2bfloat16(o2);
    hi[off]      = h1;
    hi[off + 64] = h2;
    lo[off]      = __float2bfloat16(o1 - __bfloat162float(h1));
    lo[off + 64] = __float2bfloat16(o2 - __bfloat162float(h2));
}

// ============================================================================
// Causal flash attention on mma.sync, split-bf16 3-pass both GEMMs.
// CTA: (b, h, 128-q tile); 8 warps. Output written fp32 (quantized separately).
// ============================================================================
#define AT_RS    272                       // row stride bytes (136 bf16)
#define AT_TSIZE (64*AT_RS)                // 17408 per matrix tile
#define AT_STAGE (4*AT_TSIZE)              // 69632: Kh,Kl,Vh,Vl
#define AT_SMEM  (2*AT_STAGE)              // 139264

__global__ __launch_bounds__(256)
void attn_mma_kernel(const __nv_bfloat16* __restrict__ qh,
                     const __nv_bfloat16* __restrict__ ql,
                     const __nv_bfloat16* __restrict__ kh,
                     const __nv_bfloat16* __restrict__ kl,
                     const __nv_bfloat16* __restrict__ vh,
                     const __nv_bfloat16* __restrict__ vl,
                     float* __restrict__ Of)
{
    extern __shared__ char dsm[];
    const uint32_t sb = smem_u32(dsm);
    const int tid  = threadIdx.x;
    const int lane = tid & 31, w = tid >> 5;
    const int qt = (NS/128 - 1) - blockIdx.x;   // heavy tiles first
    const int h  = blockIdx.y;
    const int b  = blockIdx.z;
    const int q0 = qt * 128;
    const long long gbase = (long long)b * NS * ND + h * HD;

    // ---- stage Q (hi then lo) into stage-0 region ----
    {
        int r = tid & 127;
        const __nv_bfloat16* src = ((tid < 128) ? qh : ql) + gbase + (long long)(q0 + r) * ND;
        uint32_t dst = sb + ((tid < 128) ? 0 : 128*AT_RS) + r * AT_RS;
#pragma unroll
        for (int c = 0; c < 16; c++) CP_ASYNC16(dst + c*16, src + c*8);
        CP_COMMIT();
        CP_WAIT0();
        __syncthreads();
    }

    // ---- Q fragments to registers (8 k16-chunks, hi+lo) ----
    uint32_t qfh[8][4], qfl[8][4];
    {
        uint32_t qaddr = sb + (w*16 + (lane & 15)) * AT_RS + (lane >> 4) * 16;
#pragma unroll
        for (int kc = 0; kc < 8; kc++) {
            LDSM4(qfh[kc], qaddr + kc*32);
            LDSM4(qfl[kc], qaddr + kc*32 + 128*AT_RS);
        }
    }
    __syncthreads();   // done reading stage-0 region

    // ---- K/V tile loader ----
    const __nv_bfloat16* kvsrc;
    {
        const __nv_bfloat16* s4[4] = {kh, kl, vh, vl};
        kvsrc = s4[tid >> 6] + gbase + (long long)(tid & 63) * ND;
    }
    const uint32_t kvdst = sb + (tid >> 6) * AT_TSIZE + (tid & 63) * AT_RS;

#define AT_ISSUE(jt, st) do { \
        const __nv_bfloat16* g = kvsrc + (long long)(jt) * 64 * ND; \
        uint32_t d = kvdst + (st) * AT_STAGE; \
        _Pragma("unroll") \
        for (int c = 0; c < 16; c++) CP_ASYNC16(d + c*16, g + c*8); \
        CP_COMMIT(); \
    } while (0)

    const int njt = 2*qt + 2;
    AT_ISSUE(0, 0);
    AT_ISSUE(1, 1);

    float m0v = -1e30f, m1v = -1e30f, l0 = 0.0f, l1 = 0.0f;
    float od[16][4];
#pragma unroll
    for (int nd = 0; nd < 16; nd++)
#pragma unroll
        for (int c = 0; c < 4; c++) od[nd][c] = 0.0f;

    for (int jt = 0; jt < njt; jt++) {
        const int st = jt & 1;
        CP_WAIT1();
        __syncthreads();
        const uint32_t kbase = sb + st * AT_STAGE;
        const uint32_t vbase = kbase + 2 * AT_TSIZE;

        // ---- S = Q·K^T (16 x 64 per warp), 3 passes ----
        float sc[8][4];
#pragma unroll
        for (int n = 0; n < 8; n++)
#pragma unroll
            for (int c = 0; c < 4; c++) sc[n][c] = 0.0f;

#pragma unroll
        for (int kc = 0; kc < 8; kc++) {
#pragma unroll
            for (int ng = 0; ng < 4; ng++) {
                uint32_t addr = kbase + (ng*16 + (lane & 15)) * AT_RS
                              + kc*32 + (lane >> 4) * 16;
                uint32_t rh[4], rl[4];
                LDSM4(rh, addr);
                LDSM4(rl, addr + AT_TSIZE);
                uint32_t b0h[2] = {rh[0], rh[2]}, b1h[2] = {rh[1], rh[3]};
                uint32_t b0l[2] = {rl[0], rl[2]}, b1l[2] = {rl[1], rl[3]};
                MMA16816(sc[2*ng],   qfh[kc], b0h);
                MMA16816(sc[2*ng],   qfh[kc], b0l);
                MMA16816(sc[2*ng],   qfl[kc], b0h);
                MMA16816(sc[2*ng+1], qfh[kc], b1h);
                MMA16816(sc[2*ng+1], qfh[kc], b1l);
                MMA16816(sc[2*ng+1], qfl[kc], b1h);
            }
        }

        // ---- causal mask (only the two diagonal k-tiles) ----
        if (jt >= njt - 2) {
            const int qrow = q0 + w*16 + (lane >> 2);
            const int kc0  = jt*64 + (lane & 3)*2;
#pragma unroll
            for (int n = 0; n < 8; n++) {
                int kcol = kc0 + n*8;
                if (kcol     > qrow)     sc[n][0] = -1e30f;
                if (kcol + 1 > qrow)     sc[n][1] = -1e30f;
                if (kcol     > qrow + 8) sc[n][2] = -1e30f;
                if (kcol + 1 > qrow + 8) sc[n][3] = -1e30f;
            }
        }

        // ---- online softmax ----
        float mx0 = -1e30f, mx1 = -1e30f;
#pragma unroll
        for (int n = 0; n < 8; n++) {
            mx0 = fmaxf(mx0, fmaxf(sc[n][0], sc[n][1]));
            mx1 = fmaxf(mx1, fmaxf(sc[n][2], sc[n][3]));
        }
        mx0 = fmaxf(mx0, __shfl_xor_sync(0xffffffffu, mx0, 1));
        mx0 = fmaxf(mx0, __shfl_xor_sync(0xffffffffu, mx0, 2));
        mx1 = fmaxf(mx1, __shfl_xor_sync(0xffffffffu, mx1, 1));
        mx1 = fmaxf(mx1, __shfl_xor_sync(0xffffffffu, mx1, 2));
        float mn0 = fmaxf(m0v, mx0), mn1 = fmaxf(m1v, mx1);
        float corr0 = __expf(m0v - mn0), corr1 = __expf(m1v - mn1);
        float ps0 = 0.0f, ps1 = 0.0f;
#pragma unroll
        for (int n = 0; n < 8; n++) {
            sc[n][0] = __expf(sc[n][0] - mn0);
            sc[n][1] = __expf(sc[n][1] - mn0);
            sc[n][2] = __expf(sc[n][2] - mn1);
            sc[n][3] = __expf(sc[n][3] - mn1);
            ps0 += sc[n][0] + sc[n][1];
            ps1 += sc[n][2] + sc[n][3];
        }
        ps0 += __shfl_xor_sync(0xffffffffu, ps0, 1);
        ps0 += __shfl_xor_sync(0xffffffffu, ps0, 2);
        ps1 += __shfl_xor_sync(0xffffffffu, ps1, 1);
        ps1 += __shfl_xor_sync(0xffffffffu, ps1, 2);
        l0 = l0 * corr0 + ps0;  m0v = mn0;
        l1 = l1 * corr1 + ps1;  m1v = mn1;
#pragma unroll
        for (int nd = 0; nd < 16; nd++) {
            od[nd][0] *= corr0; od[nd][1] *= corr0;
            od[nd][2] *= corr1; od[nd][3] *= corr1;
        }

        // ---- repack P (C-frags) into A-frags, bf16 hi/lo ----
        uint32_t pah[4][4], pal[4][4];
#pragma unroll
        for (int kc2 = 0; kc2 < 4; kc2++) {
            const int n0i = 2*kc2, n1i = 2*kc2 + 1;
            float p[4][2] = {{sc[n0i][0], sc[n0i][1]}, {sc[n0i][2], sc[n0i][3]},
                             {sc[n1i][0], sc[n1i][1]}, {sc[n1i][2], sc[n1i][3]}};
#pragma unroll
            for (int a = 0; a < 4; a++) {
                uint32_t hp = bf16x2_pack(p[a][0], p[a][1]);
                float h0 = __uint_as_float(hp << 16);
                float h1 = __uint_as_float(hp & 0xFFFF0000u);
                pah[kc2][a] = hp;
                pal[kc2][a] = bf16x2_pack(p[a][0] - h0, p[a][1] - h1);
            }
        }

        // ---- O += P·V, 3 passes ----
#pragma unroll
        for (int d0 = 0; d0 < 8; d0++) {
#pragma unroll
            for (int kc2 = 0; kc2 < 4; kc2++) {
                uint32_t addr = vbase + (kc2*16 + (lane & 15)) * AT_RS
                              + d0*32 + (lane >> 4) * 16;
                uint32_t rvh[4], rvl[4];
                LDSM4T(rvh, addr);
                LDSM4T(rvl, addr + AT_TSIZE);
                uint32_t b0h[2] = {rvh[0], rvh[1]}, b1h[2] = {rvh[2], rvh[3]};
                uint32_t b0l[2] = {rvl[0], rvl[1]}, b1l[2] = {rvl[2], rvl[3]};
                MMA16816(od[2*d0],   pah[kc2], b0h);
                MMA16816(od[2*d0],   pah[kc2], b0l);
                MMA16816(od[2*d0],   pal[kc2], b0h);
                MMA16816(od[2*d0+1], pah[kc2], b1h);
                MMA16816(od[2*d0+1], pah[kc2], b1l);
                MMA16816(od[2*d0+1], pal[kc2], b1h);
            }
        }

        __syncthreads();
        if (jt + 2 < njt) AT_ISSUE(jt + 2, st);
        else CP_COMMIT();          // keep group-count invariant for WAIT1
    }

    // ---- epilogue: O / l -> fp32 ----
    const float i0 = 1.0f / l0, i1 = 1.0f / l1;
    const long long row0 = (long long)(b*NS + q0 + w*16 + (lane >> 2)) * ND + h * HD;
    const long long row1 = row0 + 8ll * ND;
#pragma unroll
    for (int nd = 0; nd < 16; nd++) {
        const int d = nd*8 + (lane & 3)*2;
        *(float2*)&Of[row0 + d] = make_float2(od[nd][0]*i0, od[nd][1]*i0);
        *(float2*)&Of[row1 + d] = make_float2(od[nd][2]*i1, od[nd][3]*i1);
    }
#undef AT_ISSUE
}

// ============================================================================
extern "C" void kernel_launch(void* const* d_in, const int* in_sizes, int n_in,
                              void* d_out, int out_size)
{
    (void)in_sizes; (void)n_in; (void)out_size;
    const float* queries = (const float*)d_in[0];
    const float* keys    = (const float*)d_in[1];
    const float* values  = (const float*)d_in[2];
    const float* Wq = (const float*)d_in[3];
    const float* bq = (const float*)d_in[4];
    const float* Wk = (const float*)d_in[5];
    const float* bk = (const float*)d_in[6];
    const float* Wv = (const float*)d_in[7];
    const float* bv = (const float*)d_in[8];
    const float* Wo = (const float*)d_in[9];
    const float* bo = (const float*)d_in[10];
    float* out = (float*)d_out;

    float *q, *k, *wmaxv, *amaxv;
    int8_t *wh8, *wl8, *ah8, *al8;
    __nv_bfloat16 *qh, *ql, *kh, *kl, *vh, *vl;
    cudaGetSymbolAddress((void**)&q,     g_q);
    cudaGetSymbolAddress((void**)&k,     g_k);
    cudaGetSymbolAddress((void**)&wh8,   g_wh8);
    cudaGetSymbolAddress((void**)&wl8,   g_wl8);
    cudaGetSymbolAddress((void**)&wmaxv, g_wmax);
    cudaGetSymbolAddress((void**)&ah8,   g_ah8);
    cudaGetSymbolAddress((void**)&al8,   g_al8);
    cudaGetSymbolAddress((void**)&amaxv, g_amax);
    cudaGetSymbolAddress((void**)&qh,    g_qh);
    cudaGetSymbolAddress((void**)&ql,    g_ql);
    cudaGetSymbolAddress((void**)&kh,    g_kh);
    cudaGetSymbolAddress((void**)&kl,    g_kl);
    cudaGetSymbolAddress((void**)&vh,    g_vh);
    cudaGetSymbolAddress((void**)&vl,    g_vl);

    cudaFuncSetAttribute(gemm_imma_kernel,
                         cudaFuncAttributeMaxDynamicSharedMemorySize, GI_SMEM);
    cudaFuncSetAttribute(attn_mma_kernel,
                         cudaFuncAttributeMaxDynamicSharedMemorySize, AT_SMEM);

    // ---- quantize weights (transpose + 2-limb int8, per-N-row scale) ----
    const float* Ws[4] = {Wq, Wk, Wv, Wo};
    dim3 gw(ND/32, ND/32), bw(32, 8);
    for (int i = 0; i < 4; i++) {
        wmax_kernel<<<ND/32, 256>>>(Ws[i], wmaxv + i*ND);
        quant_w_kernel<<<gw, bw>>>(Ws[i], wmaxv + i*ND,
                                   wh8 + (long long)i*ND*ND, wl8 + (long long)i*ND*ND);
    }

    dim3 gtg(ND/128, NM/128);                  // (16, 32)

    // ---- projections (int8 IMMA) ----
    quant_a_kernel<<<NM, 256>>>(queries, ah8, al8, amaxv);
    gemm_imma_kernel<<<gtg, 256, GI_SMEM>>>(ah8, al8, wh8 + 0ll*ND*ND, wl8 + 0ll*ND*ND,
                                            amaxv, wmaxv + 0*ND, bq, q, nullptr, nullptr);
    quant_a_kernel<<<NM, 256>>>(keys, ah8, al8, amaxv);
    gemm_imma_kernel<<<gtg, 256, GI_SMEM>>>(ah8, al8, wh8 + 1ll*ND*ND, wl8 + 1ll*ND*ND,
                                            amaxv, wmaxv + 1*ND, bk, k, nullptr, nullptr);
    quant_a_kernel<<<NM, 256>>>(values, ah8, al8, amaxv);
    gemm_imma_kernel<<<gtg, 256, GI_SMEM>>>(ah8, al8, wh8 + 2ll*ND*ND, wl8 + 2ll*ND*ND,
                                            amaxv, wmaxv + 2*ND, bv, nullptr, vh, vl);

    // ---- RoPE + bf16 split (scale folded into Q) ----
    int nrope = NM * NH * 64;
    rope_split_kernel<<<nrope/256, 256>>>(q, qh, ql, 0.08838834764831845f);
    rope_split_kernel<<<nrope/256, 256>>>(k, kh, kl, 1.0f);

    // ---- attention (bf16 3-pass; writes fp32 O into g_q, safe to reuse) ----
    dim3 ga(NS/128, NH, NB);
    attn_mma_kernel<<<ga, 256, AT_SMEM>>>(qh, ql, kh, kl, vh, vl, q);

    // ---- output projection (int8 IMMA) ----
    quant_a_kernel<<<NM, 256>>>(q, ah8, al8, amaxv);
    gemm_imma_kernel<<<gtg, 256, GI_SMEM>>>(ah8, al8, wh8 + 3ll*ND*ND, wl8 + 3ll*ND*ND,
                                            amaxv, wmaxv + 3*ND, bo, out, nullptr, nullptr);
}

// round 10
// speedup vs baseline: 2.4092x; 2.4092x over previous
#include <cuda_runtime.h>
#include <cuda_bf16.h>
#include <cuda_fp16.h>
#include <cstdint>
#include <math.h>

#define NB 2
#define NS 2048
#define ND 2048
#define NH 16
#define HD 128
#define NM (NB*NS)   // 4096 rows

// ---- scratch (static device arrays; no allocation allowed) ----
__device__ float g_q[NM*ND];                     // fp32 Q proj (pre-rope)
__device__ float g_k[NM*ND];                     // fp32 K proj
__device__ __half g_whf[4ll*ND*ND];              // W^T hi fp16, [N][K] K-major
__device__ __half g_wlf[4ll*ND*ND];              // W^T lo fp16
__device__ __half g_af[(long long)NM*ND];        // activation fp16 (gemm A)
__device__ __half g_of[(long long)NM*ND];        // attention O fp16
__device__ __nv_bfloat16 g_qh[(long long)NM*ND]; // roped Q hi (scaled)
__device__ __nv_bfloat16 g_ql[(long long)NM*ND];
__device__ __nv_bfloat16 g_kh[(long long)NM*ND]; // roped K hi
__device__ __nv_bfloat16 g_kl[(long long)NM*ND];
__device__ __nv_bfloat16 g_vh[(long long)NM*ND]; // V proj hi
__device__ __nv_bfloat16 g_vl[(long long)NM*ND];

__device__ __forceinline__ uint32_t smem_u32(const void* p) {
    uint32_t a;
    asm("{ .reg .u64 t; cvta.to.shared.u64 t, %1; cvt.u32.u64 %0, t; }"
        : "=r"(a) : "l"(p));
    return a;
}

// ---- base-target tensor core primitives (sm_80-class, valid on compute_103) ----
#define LDSM4(r, addr) \
    asm volatile("ldmatrix.sync.aligned.m8n8.x4.shared.b16 {%0,%1,%2,%3}, [%4];" \
        : "=r"((r)[0]), "=r"((r)[1]), "=r"((r)[2]), "=r"((r)[3]) : "r"(addr))

#define LDSM4T(r, addr) \
    asm volatile("ldmatrix.sync.aligned.m8n8.x4.trans.shared.b16 {%0,%1,%2,%3}, [%4];" \
        : "=r"((r)[0]), "=r"((r)[1]), "=r"((r)[2]), "=r"((r)[3]) : "r"(addr))

#define MMA16816(d, a, b) \
    asm volatile("mma.sync.aligned.m16n8k16.row.col.f32.bf16.bf16.f32 " \
        "{%0,%1,%2,%3}, {%4,%5,%6,%7}, {%8,%9}, {%0,%1,%2,%3};" \
        : "+f"((d)[0]), "+f"((d)[1]), "+f"((d)[2]), "+f"((d)[3]) \
        : "r"((a)[0]), "r"((a)[1]), "r"((a)[2]), "r"((a)[3]), \
          "r"((b)[0]), "r"((b)[1]))

#define MMA16816H(d, a, b) \
    asm volatile("mma.sync.aligned.m16n8k16.row.col.f32.f16.f16.f32 " \
        "{%0,%1,%2,%3}, {%4,%5,%6,%7}, {%8,%9}, {%0,%1,%2,%3};" \
        : "+f"((d)[0]), "+f"((d)[1]), "+f"((d)[2]), "+f"((d)[3]) \
        : "r"((a)[0]), "r"((a)[1]), "r"((a)[2]), "r"((a)[3]), \
          "r"((b)[0]), "r"((b)[1]))

#define CP_ASYNC16(dst, src) \
    asm volatile("cp.async.cg.shared.global [%0], [%1], 16;" \
                 :: "r"(dst), "l"(src) : "memory")
#define CP_COMMIT()  asm volatile("cp.async.commit_group;" ::: "memory")
#define CP_WAIT1()   asm volatile("cp.async.wait_group 1;" ::: "memory")
#define CP_WAIT0()   asm volatile("cp.async.wait_group 0;" ::: "memory")

__device__ __forceinline__ uint32_t bf16x2_pack(float lo, float hi) {
    __nv_bfloat162 v = __floats2bfloat162_rn(lo, hi);
    return *reinterpret_cast<uint32_t*>(&v);
}
__device__ __forceinline__ uint32_t f16x2_pack(float lo, float hi) {
    __half2 v = __floats2half2_rn(lo, hi);
    return *reinterpret_cast<uint32_t*>(&v);
}

// ============================================================================
// conv_a: fp32 -> fp16 single (8 elems/thread)
// ============================================================================
__global__ void conv_a_kernel(const float* __restrict__ X, __half* __restrict__ Y)
{
    long long idx = (long long)(blockIdx.x * blockDim.x + threadIdx.x) * 8;
    float4 a = *(const float4*)(X + idx);
    float4 b = *(const float4*)(X + idx + 4);
    uint4 o;
    o.x = f16x2_pack(a.x, a.y);
    o.y = f16x2_pack(a.z, a.w);
    o.z = f16x2_pack(b.x, b.y);
    o.w = f16x2_pack(b.z, b.w);
    *(uint4*)(Y + idx) = o;
}

// ============================================================================
// split_wf: W[K][N] fp32 -> W^T hi/lo fp16 [N][K] (transpose + 2-limb split)
// ============================================================================
__global__ void split_wf_kernel(const float* __restrict__ W,
                                __half* __restrict__ hi, __half* __restrict__ lo)
{
    __shared__ float t[32][33];
    int n0 = blockIdx.x * 32, k0 = blockIdx.y * 32;
    int tx = threadIdx.x, ty = threadIdx.y;
    for (int r = ty; r < 32; r += 8)
        t[r][tx] = W[(long long)(k0 + r) * ND + n0 + tx];
    __syncthreads();
    for (int r = ty; r < 32; r += 8) {
        float x = t[tx][r];   // = W[k0+tx][n0+r]
        __half h = __float2half_rn(x);
        __half l = __float2half_rn(x - __half2float(h));
        long long o = (long long)(n0 + r) * ND + k0 + tx;
        hi[o] = h; lo[o] = l;
    }
}

// ============================================================================
// fp16 2-pass GEMM on mma.sync: C = A(f16) @ (Wh+Wl)^T + bias
// A single fp16 (one matrix), W 2-limb fp16. Shared fp32 accumulator.
// CTA 128x128, 8 warps (warp tile 64x32), K-chunk 32 f16, double buffer.
// smem rows: 64B payload, 80B stride (conflict-free ldmatrix).
// ============================================================================
#define GF_STAGE 30720                    // 3 matrices * 128 rows * 80B
#define GF_SMEM  (2*GF_STAGE)             // 61440

__global__ __launch_bounds__(256)
void gemm_f16_kernel(const __half* __restrict__ Af,
                     const __half* __restrict__ Wh,
                     const __half* __restrict__ Wl,
                     const float* __restrict__ bias,
                     float* __restrict__ C,
                     __nv_bfloat16* __restrict__ Chi,
                     __nv_bfloat16* __restrict__ Clo)
{
    extern __shared__ char dsm[];
    const uint32_t sb = smem_u32(dsm);
    const int tid  = threadIdx.x;
    const int lane = tid & 31, wid = tid >> 5;
    const int wm = wid & 1, wn = wid >> 1;      // warp tile: m 64, n 32
    const int m0 = blockIdx.y * 128, n0 = blockIdx.x * 128;

    const int lrow = tid >> 1;
    const int lc   = (tid & 1) * 16;            // elements (32B)
    const __half* gsrc[3];
    gsrc[0] = Af + (long long)(m0 + lrow) * ND + lc;
    gsrc[1] = Wh + (long long)(n0 + lrow) * ND + lc;
    gsrc[2] = Wl + (long long)(n0 + lrow) * ND + lc;
    const uint32_t sdst0 = sb + lrow * 80 + (tid & 1) * 32;

    float acc[4][4][4];
#pragma unroll
    for (int i = 0; i < 4; i++)
#pragma unroll
        for (int j = 0; j < 4; j++)
#pragma unroll
            for (int c = 0; c < 4; c++) acc[i][j][c] = 0.0f;

#define GF_ISSUE(ch, stage) do { \
        uint32_t s0 = sdst0 + (stage) * GF_STAGE; \
        _Pragma("unroll") \
        for (int m = 0; m < 3; m++) { \
            const __half* g = gsrc[m] + (ch) * 32; \
            uint32_t d = s0 + m * 10240; \
            CP_ASYNC16(d, g); \
            CP_ASYNC16(d + 16, g + 8); \
        } \
        CP_COMMIT(); \
    } while (0)

    GF_ISSUE(0, 0);
    GF_ISSUE(1, 1);

    for (int ch = 0; ch < 64; ch++) {
        const int st = ch & 1;
        CP_WAIT1();
        __syncthreads();
        const uint32_t abase = sb + st * GF_STAGE + (wm * 64) * 80
                             + (lane & 15) * 80 + (lane >> 4) * 16;
        const uint32_t bbase = sb + st * GF_STAGE + 10240 + (wn * 32) * 80
                             + (lane & 15) * 80 + (lane >> 4) * 16;
#pragma unroll
        for (int kk = 0; kk < 2; kk++) {        // two k16 steps per 32-elem chunk
            uint32_t bh[4][2], bl[4][2];
#pragma unroll
            for (int np = 0; np < 2; np++) {
                uint32_t addr = bbase + np * 1280 + kk * 32;
                uint32_t r[4], s[4];
                LDSM4(r, addr);
                LDSM4(s, addr + 10240);
                bh[np*2+0][0] = r[0]; bh[np*2+0][1] = r[2];
                bh[np*2+1][0] = r[1]; bh[np*2+1][1] = r[3];
                bl[np*2+0][0] = s[0]; bl[np*2+0][1] = s[2];
                bl[np*2+1][0] = s[1]; bl[np*2+1][1] = s[3];
            }
#pragma unroll
            for (int mt = 0; mt < 4; mt++) {
                uint32_t af[4];
                LDSM4(af, abase + mt * 1280 + kk * 32);
#pragma unroll
                for (int nt = 0; nt < 4; nt++) {
                    MMA16816H(acc[mt][nt], af, bh[nt]);
                    MMA16816H(acc[mt][nt], af, bl[nt]);
                }
            }
        }
        __syncthreads();
        if (ch + 2 < 64) GF_ISSUE(ch + 2, st);
        else CP_COMMIT();          // keep group-count invariant for WAIT1
    }

    // ---- epilogue ----
    const int r0 = m0 + wm * 64 + (lane >> 2);
    const int c0 = n0 + wn * 32 + (lane & 3) * 2;
#pragma unroll
    for (int nt = 0; nt < 4; nt++) {
        const int c = c0 + nt * 8;
        const float b0 = bias[c], b1 = bias[c + 1];
#pragma unroll
        for (int mt = 0; mt < 4; mt++) {
            const int r = r0 + mt * 16;
            float v00 = acc[mt][nt][0] + b0, v01 = acc[mt][nt][1] + b1;
            float v10 = acc[mt][nt][2] + b0, v11 = acc[mt][nt][3] + b1;
            if (C) {
                *(float2*)&C[(long long)r * ND + c]       = make_float2(v00, v01);
                *(float2*)&C[(long long)(r + 8) * ND + c] = make_float2(v10, v11);
            }
            if (Chi) {
                uint32_t h0 = bf16x2_pack(v00, v01);
                uint32_t h1 = bf16x2_pack(v10, v11);
                float h00 = __uint_as_float(h0 << 16), h01 = __uint_as_float(h0 & 0xFFFF0000u);
                float h10 = __uint_as_float(h1 << 16), h11 = __uint_as_float(h1 & 0xFFFF0000u);
                *(uint32_t*)&Chi[(long long)r * ND + c]       = h0;
                *(uint32_t*)&Chi[(long long)(r + 8) * ND + c] = h1;
                *(uint32_t*)&Clo[(long long)r * ND + c]       = bf16x2_pack(v00 - h00, v01 - h01);
                *(uint32_t*)&Clo[(long long)(r + 8) * ND + c] = bf16x2_pack(v10 - h10, v11 - h11);
            }
        }
    }
#undef GF_ISSUE
}

// ============================================================================
// RoPE + split: read fp32 proj, rotate, scale, write bf16 hi/lo
// ============================================================================
__global__ void rope_split_kernel(const float* __restrict__ X,
                                  __nv_bfloat16* __restrict__ hi,
                                  __nv_bfloat16* __restrict__ lo,
                                  float scale)
{
    int idx = blockIdx.x * blockDim.x + threadIdx.x;  // NM * NH * 64
    int i   = idx & 63;
    int h   = (idx >> 6) & (NH - 1);
    int row = idx >> 10;
    int s   = row & (NS - 1);
    float invf = powf(10000.0f, -(float)i / 64.0f);
    float ang = (float)s * invf;
    float sn, cs;
    sincosf(ang, &sn, &cs);
    long long off = (long long)row * ND + h * HD + i;
    float x1 = X[off], x2 = X[off + 64];
    float o1 = (x1 * cs - x2 * sn) * scale;
    float o2 = (x2 * cs + x1 * sn) * scale;
    __nv_bfloat16 h1 = __float2bfloat16(o1);
    __nv_bfloat16 h2 = __float2bfloat16(o2);
    hi[off]      = h1;
    hi[off + 64] = h2;
    lo[off]      = __float2bfloat16(o1 - __bfloat162float(h1));
    lo[off + 64] = __float2bfloat16(o2 - __bfloat162float(h2));
}

// ============================================================================
// Causal flash attention on mma.sync, split-bf16 3-pass both GEMMs.
// CTA: (b, h, 128-q tile); 8 warps. Output written as single fp16 (feeds
// the fp16 2-pass output projection).
// ============================================================================
#define AT_RS    272                       // row stride bytes (136 bf16)
#define AT_TSIZE (64*AT_RS)                // 17408 per matrix tile
#define AT_STAGE (4*AT_TSIZE)              // 69632: Kh,Kl,Vh,Vl
#define AT_SMEM  (2*AT_STAGE)              // 139264

__global__ __launch_bounds__(256)
void attn_mma_kernel(const __nv_bfloat16* __restrict__ qh,
                     const __nv_bfloat16* __restrict__ ql,
                     const __nv_bfloat16* __restrict__ kh,
                     const __nv_bfloat16* __restrict__ kl,
                     const __nv_bfloat16* __restrict__ vh,
                     const __nv_bfloat16* __restrict__ vl,
                     __half* __restrict__ of)
{
    extern __shared__ char dsm[];
    const uint32_t sb = smem_u32(dsm);
    const int tid  = threadIdx.x;
    const int lane = tid & 31, w = tid >> 5;
    const int qt = (NS/128 - 1) - blockIdx.x;   // heavy tiles first
    const int h  = blockIdx.y;
    const int b  = blockIdx.z;
    const int q0 = qt * 128;
    const long long gbase = (long long)b * NS * ND + h * HD;

    // ---- stage Q (hi then lo) into stage-0 region ----
    {
        int r = tid & 127;
        const __nv_bfloat16* src = ((tid < 128) ? qh : ql) + gbase + (long long)(q0 + r) * ND;
        uint32_t dst = sb + ((tid < 128) ? 0 : 128*AT_RS) + r * AT_RS;
#pragma unroll
        for (int c = 0; c < 16; c++) CP_ASYNC16(dst + c*16, src + c*8);
        CP_COMMIT();
        CP_WAIT0();
        __syncthreads();
    }

    // ---- Q fragments to registers (8 k16-chunks, hi+lo) ----
    uint32_t qfh[8][4], qfl[8][4];
    {
        uint32_t qaddr = sb + (w*16 + (lane & 15)) * AT_RS + (lane >> 4) * 16;
#pragma unroll
        for (int kc = 0; kc < 8; kc++) {
            LDSM4(qfh[kc], qaddr + kc*32);
            LDSM4(qfl[kc], qaddr + kc*32 + 128*AT_RS);
        }
    }
    __syncthreads();   // done reading stage-0 region

    // ---- K/V tile loader ----
    const __nv_bfloat16* kvsrc;
    {
        const __nv_bfloat16* s4[4] = {kh, kl, vh, vl};
        kvsrc = s4[tid >> 6] + gbase + (long long)(tid & 63) * ND;
    }
    const uint32_t kvdst = sb + (tid >> 6) * AT_TSIZE + (tid & 63) * AT_RS;

#define AT_ISSUE(jt, st) do { \
        const __nv_bfloat16* g = kvsrc + (long long)(jt) * 64 * ND; \
        uint32_t d = kvdst + (st) * AT_STAGE; \
        _Pragma("unroll") \
        for (int c = 0; c < 16; c++) CP_ASYNC16(d + c*16, g + c*8); \
        CP_COMMIT(); \
    } while (0)

    const int njt = 2*qt + 2;
    AT_ISSUE(0, 0);
    AT_ISSUE(1, 1);

    float m0v = -1e30f, m1v = -1e30f, l0 = 0.0f, l1 = 0.0f;
    float od[16][4];
#pragma unroll
    for (int nd = 0; nd < 16; nd++)
#pragma unroll
        for (int c = 0; c < 4; c++) od[nd][c] = 0.0f;

    for (int jt = 0; jt < njt; jt++) {
        const int st = jt & 1;
        CP_WAIT1();
        __syncthreads();
        const uint32_t kbase = sb + st * AT_STAGE;
        const uint32_t vbase = kbase + 2 * AT_TSIZE;

        // ---- S = Q·K^T (16 x 64 per warp), 3 passes ----
        float sc[8][4];
#pragma unroll
        for (int n = 0; n < 8; n++)
#pragma unroll
            for (int c = 0; c < 4; c++) sc[n][c] = 0.0f;

#pragma unroll
        for (int kc = 0; kc < 8; kc++) {
#pragma unroll
            for (int ng = 0; ng < 4; ng++) {
                uint32_t addr = kbase + (ng*16 + (lane & 15)) * AT_RS
                              + kc*32 + (lane >> 4) * 16;
                uint32_t rh[4], rl[4];
                LDSM4(rh, addr);
                LDSM4(rl, addr + AT_TSIZE);
                uint32_t b0h[2] = {rh[0], rh[2]}, b1h[2] = {rh[1], rh[3]};
                uint32_t b0l[2] = {rl[0], rl[2]}, b1l[2] = {rl[1], rl[3]};
                MMA16816(sc[2*ng],   qfh[kc], b0h);
                MMA16816(sc[2*ng],   qfh[kc], b0l);
                MMA16816(sc[2*ng],   qfl[kc], b0h);
                MMA16816(sc[2*ng+1], qfh[kc], b1h);
                MMA16816(sc[2*ng+1], qfh[kc], b1l);
                MMA16816(sc[2*ng+1], qfl[kc], b1h);
            }
        }

        // ---- causal mask (only the two diagonal k-tiles) ----
        if (jt >= njt - 2) {
            const int qrow = q0 + w*16 + (lane >> 2);
            const int kc0  = jt*64 + (lane & 3)*2;
#pragma unroll
            for (int n = 0; n < 8; n++) {
                int kcol = kc0 + n*8;
                if (kcol     > qrow)     sc[n][0] = -1e30f;
                if (kcol + 1 > qrow)     sc[n][1] = -1e30f;
                if (kcol     > qrow + 8) sc[n][2] = -1e30f;
                if (kcol + 1 > qrow + 8) sc[n][3] = -1e30f;
            }
        }

        // ---- online softmax ----
        float mx0 = -1e30f, mx1 = -1e30f;
#pragma unroll
        for (int n = 0; n < 8; n++) {
            mx0 = fmaxf(mx0, fmaxf(sc[n][0], sc[n][1]));
            mx1 = fmaxf(mx1, fmaxf(sc[n][2], sc[n][3]));
        }
        mx0 = fmaxf(mx0, __shfl_xor_sync(0xffffffffu, mx0, 1));
        mx0 = fmaxf(mx0, __shfl_xor_sync(0xffffffffu, mx0, 2));
        mx1 = fmaxf(mx1, __shfl_xor_sync(0xffffffffu, mx1, 1));
        mx1 = fmaxf(mx1, __shfl_xor_sync(0xffffffffu, mx1, 2));
        float mn0 = fmaxf(m0v, mx0), mn1 = fmaxf(m1v, mx1);
        float corr0 = __expf(m0v - mn0), corr1 = __expf(m1v - mn1);
        float ps0 = 0.0f, ps1 = 0.0f;
#pragma unroll
        for (int n = 0; n < 8; n++) {
            sc[n][0] = __expf(sc[n][0] - mn0);
            sc[n][1] = __expf(sc[n][1] - mn0);
            sc[n][2] = __expf(sc[n][2] - mn1);
            sc[n][3] = __expf(sc[n][3] - mn1);
            ps0 += sc[n][0] + sc[n][1];
            ps1 += sc[n][2] + sc[n][3];
        }
        ps0 += __shfl_xor_sync(0xffffffffu, ps0, 1);
        ps0 += __shfl_xor_sync(0xffffffffu, ps0, 2);
        ps1 += __shfl_xor_sync(0xffffffffu, ps1, 1);
        ps1 += __shfl_xor_sync(0xffffffffu, ps1, 2);
        l0 = l0 * corr0 + ps0;  m0v = mn0;
        l1 = l1 * corr1 + ps1;  m1v = mn1;
#pragma unroll
        for (int nd = 0; nd < 16; nd++) {
            od[nd][0] *= corr0; od[nd][1] *= corr0;
            od[nd][2] *= corr1; od[nd][3] *= corr1;
        }

        // ---- repack P (C-frags) into A-frags, bf16 hi/lo ----
        uint32_t pah[4][4], pal[4][4];
#pragma unroll
        for (int kc2 = 0; kc2 < 4; kc2++) {
            const int n0i = 2*kc2, n1i = 2*kc2 + 1;
            float p[4][2] = {{sc[n0i][0], sc[n0i][1]}, {sc[n0i][2], sc[n0i][3]},
                             {sc[n1i][0], sc[n1i][1]}, {sc[n1i][2], sc[n1i][3]}};
#pragma unroll
            for (int a = 0; a < 4; a++) {
                uint32_t hp = bf16x2_pack(p[a][0], p[a][1]);
                float h0 = __uint_as_float(hp << 16);
                float h1 = __uint_as_float(hp & 0xFFFF0000u);
                pah[kc2][a] = hp;
                pal[kc2][a] = bf16x2_pack(p[a][0] - h0, p[a][1] - h1);
            }
        }

        // ---- O += P·V, 3 passes ----
#pragma unroll
        for (int d0 = 0; d0 < 8; d0++) {
#pragma unroll
            for (int kc2 = 0; kc2 < 4; kc2++) {
                uint32_t addr = vbase + (kc2*16 + (lane & 15)) * AT_RS
                              + d0*32 + (lane >> 4) * 16;
                uint32_t rvh[4], rvl[4];
                LDSM4T(rvh, addr);
                LDSM4T(rvl, addr + AT_TSIZE);
                uint32_t b0h[2] = {rvh[0], rvh[1]}, b1h[2] = {rvh[2], rvh[3]};
                uint32_t b0l[2] = {rvl[0], rvl[1]}, b1l[2] = {rvl[2], rvl[3]};
                MMA16816(od[2*d0],   pah[kc2], b0h);
                MMA16816(od[2*d0],   pah[kc2], b0l);
                MMA16816(od[2*d0],   pal[kc2], b0h);
                MMA16816(od[2*d0+1], pah[kc2], b1h);
                MMA16816(od[2*d0+1], pah[kc2], b1l);
                MMA16816(od[2*d0+1], pal[kc2], b1h);
            }
        }

        __syncthreads();
        if (jt + 2 < njt) AT_ISSUE(jt + 2, st);
        else CP_COMMIT();          // keep group-count invariant for WAIT1
    }

    // ---- epilogue: O / l -> fp16 ----
    const float i0 = 1.0f / l0, i1 = 1.0f / l1;
    const long long row0 = (long long)(b*NS + q0 + w*16 + (lane >> 2)) * ND + h * HD;
    const long long row1 = row0 + 8ll * ND;
#pragma unroll
    for (int nd = 0; nd < 16; nd++) {
        const int d = nd*8 + (lane & 3)*2;
        *(uint32_t*)&of[row0 + d] = f16x2_pack(od[nd][0]*i0, od[nd][1]*i0);
        *(uint32_t*)&of[row1 + d] = f16x2_pack(od[nd][2]*i1, od[nd][3]*i1);
    }
#undef AT_ISSUE
}

// ============================================================================
extern "C" void kernel_launch(void* const* d_in, const int* in_sizes, int n_in,
                              void* d_out, int out_size)
{
    (void)in_sizes; (void)n_in; (void)out_size;
    const float* queries = (const float*)d_in[0];
    const float* keys    = (const float*)d_in[1];
    const float* values  = (const float*)d_in[2];
    const float* Wq = (const float*)d_in[3];
    const float* bq = (const float*)d_in[4];
    const float* Wk = (const float*)d_in[5];
    const float* bk = (const float*)d_in[6];
    const float* Wv = (const float*)d_in[7];
    const float* bv = (const float*)d_in[8];
    const float* Wo = (const float*)d_in[9];
    const float* bo = (const float*)d_in[10];
    float* out = (float*)d_out;

    float *q, *k;
    __half *whf, *wlf, *af, *of;
    __nv_bfloat16 *qh, *ql, *kh, *kl, *vh, *vl;
    cudaGetSymbolAddress((void**)&q,   g_q);
    cudaGetSymbolAddress((void**)&k,   g_k);
    cudaGetSymbolAddress((void**)&whf, g_whf);
    cudaGetSymbolAddress((void**)&wlf, g_wlf);
    cudaGetSymbolAddress((void**)&af,  g_af);
    cudaGetSymbolAddress((void**)&of,  g_of);
    cudaGetSymbolAddress((void**)&qh,  g_qh);
    cudaGetSymbolAddress((void**)&ql,  g_ql);
    cudaGetSymbolAddress((void**)&kh,  g_kh);
    cudaGetSymbolAddress((void**)&kl,  g_kl);
    cudaGetSymbolAddress((void**)&vh,  g_vh);
    cudaGetSymbolAddress((void**)&vl,  g_vl);

    cudaFuncSetAttribute(gemm_f16_kernel,
                         cudaFuncAttributeMaxDynamicSharedMemorySize, GF_SMEM);
    cudaFuncSetAttribute(attn_mma_kernel,
                         cudaFuncAttributeMaxDynamicSharedMemorySize, AT_SMEM);

    // ---- split + transpose weights (fp16 2-limb) ----
    const float* Ws[4] = {Wq, Wk, Wv, Wo};
    dim3 gw(ND/32, ND/32), bw(32, 8);
    for (int i = 0; i < 4; i++)
        split_wf_kernel<<<gw, bw>>>(Ws[i], whf + (long long)i*ND*ND,
                                           wlf + (long long)i*ND*ND);

    const int nconv = NM*ND/8/256;
    dim3 gtg(ND/128, NM/128);                  // (16, 32)

    // ---- projections (fp16 2-pass) ----
    conv_a_kernel<<<nconv, 256>>>(queries, af);
    gemm_f16_kernel<<<gtg, 256, GF_SMEM>>>(af, whf + 0ll*ND*ND, wlf + 0ll*ND*ND,
                                           bq, q, nullptr, nullptr);
    conv_a_kernel<<<nconv, 256>>>(keys, af);
    gemm_f16_kernel<<<gtg, 256, GF_SMEM>>>(af, whf + 1ll*ND*ND, wlf + 1ll*ND*ND,
                                           bk, k, nullptr, nullptr);
    conv_a_kernel<<<nconv, 256>>>(values, af);
    gemm_f16_kernel<<<gtg, 256, GF_SMEM>>>(af, whf + 2ll*ND*ND, wlf + 2ll*ND*ND,
                                           bv, nullptr, vh, vl);

    // ---- RoPE + bf16 split (scale folded into Q) ----
    int nrope = NM * NH * 64;
    rope_split_kernel<<<nrope/256, 256>>>(q, qh, ql, 0.08838834764831845f);
    rope_split_kernel<<<nrope/256, 256>>>(k, kh, kl, 1.0f);

    // ---- attention (bf16 3-pass; writes fp16 O) ----
    dim3 ga(NS/128, NH, NB);
    attn_mma_kernel<<<ga, 256, AT_SMEM>>>(qh, ql, kh, kl, vh, vl, of);

    // ---- output projection (fp16 2-pass) ----
    gemm_f16_kernel<<<gtg, 256, GF_SMEM>>>(of, whf + 3ll*ND*ND, wlf + 3ll*ND*ND,
                                           bo, out, nullptr, nullptr);
}

// round 11
// speedup vs baseline: 3.8277x; 1.5888x over previous
#include <cuda_runtime.h>
#include <cuda_bf16.h>
#include <cuda_fp16.h>
#include <cstdint>
#include <math.h>

#define NB 2
#define NS 2048
#define ND 2048
#define NH 16
#define HD 128
#define NM (NB*NS)   // 4096 rows

// ---- scratch (static device arrays; no allocation allowed) ----
__device__ float g_q[NM*ND];                 // fp32 Q proj (pre-rope)
__device__ float g_k[NM*ND];                 // fp32 K proj
__device__ __half g_whf[4ll*ND*ND];          // W^T fp16 single, [N][K] K-major
__device__ __half g_af[(long long)NM*ND];    // activation fp16 (gemm A)
__device__ __half g_of[(long long)NM*ND];    // attention O fp16
__device__ __half g_qh[(long long)NM*ND];    // roped Q hi fp16 (scaled)
__device__ __half g_ql[(long long)NM*ND];    // roped Q lo fp16
__device__ __half g_kf[(long long)NM*ND];    // roped K single fp16
__device__ __half g_vh[(long long)NM*ND];    // V proj hi fp16
__device__ __half g_vl[(long long)NM*ND];    // V proj lo fp16

__device__ __forceinline__ uint32_t smem_u32(const void* p) {
    uint32_t a;
    asm("{ .reg .u64 t; cvta.to.shared.u64 t, %1; cvt.u32.u64 %0, t; }"
        : "=r"(a) : "l"(p));
    return a;
}

// ---- base-target tensor core primitives (sm_80-class, valid on compute_103) ----
#define LDSM4(r, addr) \
    asm volatile("ldmatrix.sync.aligned.m8n8.x4.shared.b16 {%0,%1,%2,%3}, [%4];" \
        : "=r"((r)[0]), "=r"((r)[1]), "=r"((r)[2]), "=r"((r)[3]) : "r"(addr))

#define LDSM4T(r, addr) \
    asm volatile("ldmatrix.sync.aligned.m8n8.x4.trans.shared.b16 {%0,%1,%2,%3}, [%4];" \
        : "=r"((r)[0]), "=r"((r)[1]), "=r"((r)[2]), "=r"((r)[3]) : "r"(addr))

#define MMA16816H(d, a, b) \
    asm volatile("mma.sync.aligned.m16n8k16.row.col.f32.f16.f16.f32 " \
        "{%0,%1,%2,%3}, {%4,%5,%6,%7}, {%8,%9}, {%0,%1,%2,%3};" \
        : "+f"((d)[0]), "+f"((d)[1]), "+f"((d)[2]), "+f"((d)[3]) \
        : "r"((a)[0]), "r"((a)[1]), "r"((a)[2]), "r"((a)[3]), \
          "r"((b)[0]), "r"((b)[1]))

#define CP_ASYNC16(dst, src) \
    asm volatile("cp.async.cg.shared.global [%0], [%1], 16;" \
                 :: "r"(dst), "l"(src) : "memory")
#define CP_COMMIT()  asm volatile("cp.async.commit_group;" ::: "memory")
#define CP_WAIT1()   asm volatile("cp.async.wait_group 1;" ::: "memory")
#define CP_WAIT0()   asm volatile("cp.async.wait_group 0;" ::: "memory")

__device__ __forceinline__ uint32_t f16x2_pack(float lo, float hi) {
    __half2 v = __floats2half2_rn(lo, hi);
    return *reinterpret_cast<uint32_t*>(&v);
}

// ============================================================================
// conv_a: fp32 -> fp16 single (8 elems/thread)
// ============================================================================
__global__ void conv_a_kernel(const float* __restrict__ X, __half* __restrict__ Y)
{
    long long idx = (long long)(blockIdx.x * blockDim.x + threadIdx.x) * 8;
    float4 a = *(const float4*)(X + idx);
    float4 b = *(const float4*)(X + idx + 4);
    uint4 o;
    o.x = f16x2_pack(a.x, a.y);
    o.y = f16x2_pack(a.z, a.w);
    o.z = f16x2_pack(b.x, b.y);
    o.w = f16x2_pack(b.z, b.w);
    *(uint4*)(Y + idx) = o;
}

// ============================================================================
// conv_w: W[K][N] fp32 -> W^T fp16 single [N][K] (transpose)
// ============================================================================
__global__ void conv_w_kernel(const float* __restrict__ W, __half* __restrict__ Wt)
{
    __shared__ float t[32][33];
    int n0 = blockIdx.x * 32, k0 = blockIdx.y * 32;
    int tx = threadIdx.x, ty = threadIdx.y;
    for (int r = ty; r < 32; r += 8)
        t[r][tx] = W[(long long)(k0 + r) * ND + n0 + tx];
    __syncthreads();
    for (int r = ty; r < 32; r += 8)
        Wt[(long long)(n0 + r) * ND + k0 + tx] = __float2half_rn(t[tx][r]);
}

// ============================================================================
// 1-pass fp16 GEMM on mma.sync: C = A(f16) @ W^T(f16) + bias
// Outputs fp32 C and/or fp16 hi/lo limbs (for V).
// CTA 128x128, 8 warps (warp tile 64x32), K-chunk 32 f16, double buffer.
// smem rows: 64B payload, 80B stride (conflict-free ldmatrix).
// ============================================================================
#define GF_STAGE 20480                    // 2 matrices * 128 rows * 80B
#define GF_SMEM  (2*GF_STAGE)             // 40960

__global__ __launch_bounds__(256)
void gemm_f16_kernel(const __half* __restrict__ Af,
                     const __half* __restrict__ Wf,
                     const float* __restrict__ bias,
                     float* __restrict__ C,
                     __half* __restrict__ Chi,
                     __half* __restrict__ Clo)
{
    extern __shared__ char dsm[];
    const uint32_t sb = smem_u32(dsm);
    const int tid  = threadIdx.x;
    const int lane = tid & 31, wid = tid >> 5;
    const int wm = wid & 1, wn = wid >> 1;      // warp tile: m 64, n 32
    const int m0 = blockIdx.y * 128, n0 = blockIdx.x * 128;

    const int lrow = tid >> 1;
    const int lc   = (tid & 1) * 16;            // elements (32B)
    const __half* gsrc[2];
    gsrc[0] = Af + (long long)(m0 + lrow) * ND + lc;
    gsrc[1] = Wf + (long long)(n0 + lrow) * ND + lc;
    const uint32_t sdst0 = sb + lrow * 80 + (tid & 1) * 32;

    float acc[4][4][4];
#pragma unroll
    for (int i = 0; i < 4; i++)
#pragma unroll
        for (int j = 0; j < 4; j++)
#pragma unroll
            for (int c = 0; c < 4; c++) acc[i][j][c] = 0.0f;

#define GF_ISSUE(ch, stage) do { \
        uint32_t s0 = sdst0 + (stage) * GF_STAGE; \
        _Pragma("unroll") \
        for (int m = 0; m < 2; m++) { \
            const __half* g = gsrc[m] + (ch) * 32; \
            uint32_t d = s0 + m * 10240; \
            CP_ASYNC16(d, g); \
            CP_ASYNC16(d + 16, g + 8); \
        } \
        CP_COMMIT(); \
    } while (0)

    GF_ISSUE(0, 0);
    GF_ISSUE(1, 1);

    for (int ch = 0; ch < 64; ch++) {
        const int st = ch & 1;
        CP_WAIT1();
        __syncthreads();
        const uint32_t abase = sb + st * GF_STAGE + (wm * 64) * 80
                             + (lane & 15) * 80 + (lane >> 4) * 16;
        const uint32_t bbase = sb + st * GF_STAGE + 10240 + (wn * 32) * 80
                             + (lane & 15) * 80 + (lane >> 4) * 16;
#pragma unroll
        for (int kk = 0; kk < 2; kk++) {        // two k16 steps per 32-elem chunk
            uint32_t bh[4][2];
#pragma unroll
            for (int np = 0; np < 2; np++) {
                uint32_t r[4];
                LDSM4(r, bbase + np * 1280 + kk * 32);
                bh[np*2+0][0] = r[0]; bh[np*2+0][1] = r[2];
                bh[np*2+1][0] = r[1]; bh[np*2+1][1] = r[3];
            }
#pragma unroll
            for (int mt = 0; mt < 4; mt++) {
                uint32_t af[4];
                LDSM4(af, abase + mt * 1280 + kk * 32);
#pragma unroll
                for (int nt = 0; nt < 4; nt++)
                    MMA16816H(acc[mt][nt], af, bh[nt]);
            }
        }
        __syncthreads();
        if (ch + 2 < 64) GF_ISSUE(ch + 2, st);
        else CP_COMMIT();          // keep group-count invariant for WAIT1
    }

    // ---- epilogue ----
    const int r0 = m0 + wm * 64 + (lane >> 2);
    const int c0 = n0 + wn * 32 + (lane & 3) * 2;
#pragma unroll
    for (int nt = 0; nt < 4; nt++) {
        const int c = c0 + nt * 8;
        const float b0 = bias[c], b1 = bias[c + 1];
#pragma unroll
        for (int mt = 0; mt < 4; mt++) {
            const int r = r0 + mt * 16;
            float v00 = acc[mt][nt][0] + b0, v01 = acc[mt][nt][1] + b1;
            float v10 = acc[mt][nt][2] + b0, v11 = acc[mt][nt][3] + b1;
            if (C) {
                *(float2*)&C[(long long)r * ND + c]       = make_float2(v00, v01);
                *(float2*)&C[(long long)(r + 8) * ND + c] = make_float2(v10, v11);
            }
            if (Chi) {
                uint32_t h0 = f16x2_pack(v00, v01);
                uint32_t h1 = f16x2_pack(v10, v11);
                __half2 hh0 = *reinterpret_cast<__half2*>(&h0);
                __half2 hh1 = *reinterpret_cast<__half2*>(&h1);
                float h00 = __half2float(hh0.x), h01 = __half2float(hh0.y);
                float h10 = __half2float(hh1.x), h11 = __half2float(hh1.y);
                *(uint32_t*)&Chi[(long long)r * ND + c]       = h0;
                *(uint32_t*)&Chi[(long long)(r + 8) * ND + c] = h1;
                *(uint32_t*)&Clo[(long long)r * ND + c]       = f16x2_pack(v00 - h00, v01 - h01);
                *(uint32_t*)&Clo[(long long)(r + 8) * ND + c] = f16x2_pack(v10 - h10, v11 - h11);
            }
        }
    }
#undef GF_ISSUE
}

// ============================================================================
// RoPE kernels: fp32 proj -> rotated fp16.
// rope2f: 2-limb hi/lo (Q, with 1/sqrt(HD) scale folded in)
// rope1f: single fp16 (K)
// ============================================================================
__global__ void rope2f_kernel(const float* __restrict__ X,
                              __half* __restrict__ hi, __half* __restrict__ lo,
                              float scale)
{
    int idx = blockIdx.x * blockDim.x + threadIdx.x;  // NM * NH * 64
    int i   = idx & 63;
    int h   = (idx >> 6) & (NH - 1);
    int row = idx >> 10;
    int s   = row & (NS - 1);
    float invf = powf(10000.0f, -(float)i / 64.0f);
    float ang = (float)s * invf;
    float sn, cs;
    sincosf(ang, &sn, &cs);
    long long off = (long long)row * ND + h * HD + i;
    float x1 = X[off], x2 = X[off + 64];
    float o1 = (x1 * cs - x2 * sn) * scale;
    float o2 = (x2 * cs + x1 * sn) * scale;
    __half h1 = __float2half_rn(o1);
    __half h2 = __float2half_rn(o2);
    hi[off]      = h1;
    hi[off + 64] = h2;
    lo[off]      = __float2half_rn(o1 - __half2float(h1));
    lo[off + 64] = __float2half_rn(o2 - __half2float(h2));
}

__global__ void rope1f_kernel(const float* __restrict__ X, __half* __restrict__ Y)
{
    int idx = blockIdx.x * blockDim.x + threadIdx.x;
    int i   = idx & 63;
    int h   = (idx >> 6) & (NH - 1);
    int row = idx >> 10;
    int s   = row & (NS - 1);
    float invf = powf(10000.0f, -(float)i / 64.0f);
    float ang = (float)s * invf;
    float sn, cs;
    sincosf(ang, &sn, &cs);
    long long off = (long long)row * ND + h * HD + i;
    float x1 = X[off], x2 = X[off + 64];
    Y[off]      = __float2half_rn(x1 * cs - x2 * sn);
    Y[off + 64] = __float2half_rn(x2 * cs + x1 * sn);
}

// ============================================================================
// Causal flash attention on mma.sync, fp16 2-pass both GEMMs:
//   QK^T = (Qh + Ql) x K_single   (2 MMA passes)
//   O   += P_single x (Vh + Vl)   (2 MMA passes)
// CTA: (b, h, 128-q tile); 8 warps. K/V stage = 3 tiles (K, Vh, Vl).
// Output single fp16 (feeds the 1-pass output projection).
// ============================================================================
#define AT_RS    272                       // row stride bytes (136 fp16)
#define AT_TSIZE (64*AT_RS)                // 17408 per matrix tile
#define AT_STAGE (3*AT_TSIZE)              // 52224: K, Vh, Vl
#define AT_SMEM  (2*AT_STAGE)              // 104448

__global__ __launch_bounds__(256)
void attn_mma_kernel(const __half* __restrict__ qh,
                     const __half* __restrict__ ql,
                     const __half* __restrict__ kf,
                     const __half* __restrict__ vh,
                     const __half* __restrict__ vl,
                     __half* __restrict__ of)
{
    extern __shared__ char dsm[];
    const uint32_t sb = smem_u32(dsm);
    const int tid  = threadIdx.x;
    const int lane = tid & 31, w = tid >> 5;
    const int qt = (NS/128 - 1) - blockIdx.x;   // heavy tiles first
    const int h  = blockIdx.y;
    const int b  = blockIdx.z;
    const int q0 = qt * 128;
    const long long gbase = (long long)b * NS * ND + h * HD;

    // ---- stage Q (hi then lo) into low smem (spans stage0 + part of stage1,
    //      consumed into registers before any K/V issue) ----
    {
        int r = tid & 127;
        const __half* src = ((tid < 128) ? qh : ql) + gbase + (long long)(q0 + r) * ND;
        uint32_t dst = sb + ((tid < 128) ? 0 : 128*AT_RS) + r * AT_RS;
#pragma unroll
        for (int c = 0; c < 16; c++) CP_ASYNC16(dst + c*16, src + c*8);
        CP_COMMIT();
        CP_WAIT0();
        __syncthreads();
    }

    // ---- Q fragments to registers (8 k16-chunks, hi+lo) ----
    uint32_t qfh[8][4], qfl[8][4];
    {
        uint32_t qaddr = sb + (w*16 + (lane & 15)) * AT_RS + (lane >> 4) * 16;
#pragma unroll
        for (int kc = 0; kc < 8; kc++) {
            LDSM4(qfh[kc], qaddr + kc*32);
            LDSM4(qfl[kc], qaddr + kc*32 + 128*AT_RS);
        }
    }
    __syncthreads();   // done reading Q staging region

    // ---- K/V tile loader: 3 matrices x 64 rows, threads 0..191 ----
    const __half* kvsrc = nullptr;
    uint32_t kvdst = 0;
    const bool loader = (tid < 192);
    if (loader) {
        const __half* s3[3] = {kf, vh, vl};
        kvsrc = s3[tid >> 6] + gbase + (long long)(tid & 63) * ND;
        kvdst = sb + (tid >> 6) * AT_TSIZE + (tid & 63) * AT_RS;
    }

#define AT_ISSUE(jt, st) do { \
        if (loader) { \
            const __half* g = kvsrc + (long long)(jt) * 64 * ND; \
            uint32_t d = kvdst + (st) * AT_STAGE; \
            _Pragma("unroll") \
            for (int c = 0; c < 16; c++) CP_ASYNC16(d + c*16, g + c*8); \
        } \
        CP_COMMIT(); \
    } while (0)

    const int njt = 2*qt + 2;
    AT_ISSUE(0, 0);
    AT_ISSUE(1, 1);

    float m0v = -1e30f, m1v = -1e30f, l0 = 0.0f, l1 = 0.0f;
    float od[16][4];
#pragma unroll
    for (int nd = 0; nd < 16; nd++)
#pragma unroll
        for (int c = 0; c < 4; c++) od[nd][c] = 0.0f;

    for (int jt = 0; jt < njt; jt++) {
        const int st = jt & 1;
        CP_WAIT1();
        __syncthreads();
        const uint32_t kbase = sb + st * AT_STAGE;
        const uint32_t vbase = kbase + AT_TSIZE;      // Vh; Vl at +AT_TSIZE more

        // ---- S = Q·K^T (16 x 64 per warp), 2 passes ----
        float sc[8][4];
#pragma unroll
        for (int n = 0; n < 8; n++)
#pragma unroll
            for (int c = 0; c < 4; c++) sc[n][c] = 0.0f;

#pragma unroll
        for (int kc = 0; kc < 8; kc++) {
#pragma unroll
            for (int ng = 0; ng < 4; ng++) {
                uint32_t rk[4];
                LDSM4(rk, kbase + (ng*16 + (lane & 15)) * AT_RS
                          + kc*32 + (lane >> 4) * 16);
                uint32_t b0[2] = {rk[0], rk[2]}, b1[2] = {rk[1], rk[3]};
                MMA16816H(sc[2*ng],   qfh[kc], b0);
                MMA16816H(sc[2*ng],   qfl[kc], b0);
                MMA16816H(sc[2*ng+1], qfh[kc], b1);
                MMA16816H(sc[2*ng+1], qfl[kc], b1);
            }
        }

        // ---- causal mask (only the two diagonal k-tiles) ----
        if (jt >= njt - 2) {
            const int qrow = q0 + w*16 + (lane >> 2);
            const int kc0  = jt*64 + (lane & 3)*2;
#pragma unroll
            for (int n = 0; n < 8; n++) {
                int kcol = kc0 + n*8;
                if (kcol     > qrow)     sc[n][0] = -1e30f;
                if (kcol + 1 > qrow)     sc[n][1] = -1e30f;
                if (kcol     > qrow + 8) sc[n][2] = -1e30f;
                if (kcol + 1 > qrow + 8) sc[n][3] = -1e30f;
            }
        }

        // ---- online softmax ----
        float mx0 = -1e30f, mx1 = -1e30f;
#pragma unroll
        for (int n = 0; n < 8; n++) {
            mx0 = fmaxf(mx0, fmaxf(sc[n][0], sc[n][1]));
            mx1 = fmaxf(mx1, fmaxf(sc[n][2], sc[n][3]));
        }
        mx0 = fmaxf(mx0, __shfl_xor_sync(0xffffffffu, mx0, 1));
        mx0 = fmaxf(mx0, __shfl_xor_sync(0xffffffffu, mx0, 2));
        mx1 = fmaxf(mx1, __shfl_xor_sync(0xffffffffu, mx1, 1));
        mx1 = fmaxf(mx1, __shfl_xor_sync(0xffffffffu, mx1, 2));
        float mn0 = fmaxf(m0v, mx0), mn1 = fmaxf(m1v, mx1);
        float corr0 = __expf(m0v - mn0), corr1 = __expf(m1v - mn1);
        float ps0 = 0.0f, ps1 = 0.0f;
#pragma unroll
        for (int n = 0; n < 8; n++) {
            sc[n][0] = __expf(sc[n][0] - mn0);
            sc[n][1] = __expf(sc[n][1] - mn0);
            sc[n][2] = __expf(sc[n][2] - mn1);
            sc[n][3] = __expf(sc[n][3] - mn1);
            ps0 += sc[n][0] + sc[n][1];
            ps1 += sc[n][2] + sc[n][3];
        }
        ps0 += __shfl_xor_sync(0xffffffffu, ps0, 1);
        ps0 += __shfl_xor_sync(0xffffffffu, ps0, 2);
        ps1 += __shfl_xor_sync(0xffffffffu, ps1, 1);
        ps1 += __shfl_xor_sync(0xffffffffu, ps1, 2);
        l0 = l0 * corr0 + ps0;  m0v = mn0;
        l1 = l1 * corr1 + ps1;  m1v = mn1;
#pragma unroll
        for (int nd = 0; nd < 16; nd++) {
            od[nd][0] *= corr0; od[nd][1] *= corr0;
            od[nd][2] *= corr1; od[nd][3] *= corr1;
        }

        // ---- repack P (C-frags) into single-fp16 A-frags ----
        uint32_t pa[4][4];
#pragma unroll
        for (int kc2 = 0; kc2 < 4; kc2++) {
            const int n0i = 2*kc2, n1i = 2*kc2 + 1;
            pa[kc2][0] = f16x2_pack(sc[n0i][0], sc[n0i][1]);
            pa[kc2][1] = f16x2_pack(sc[n0i][2], sc[n0i][3]);
            pa[kc2][2] = f16x2_pack(sc[n1i][0], sc[n1i][1]);
            pa[kc2][3] = f16x2_pack(sc[n1i][2], sc[n1i][3]);
        }

        // ---- O += P·(Vh+Vl), 2 passes ----
#pragma unroll
        for (int d0 = 0; d0 < 8; d0++) {
#pragma unroll
            for (int kc2 = 0; kc2 < 4; kc2++) {
                uint32_t addr = vbase + (kc2*16 + (lane & 15)) * AT_RS
                              + d0*32 + (lane >> 4) * 16;
                uint32_t rvh[4], rvl[4];
                LDSM4T(rvh, addr);
                LDSM4T(rvl, addr + AT_TSIZE);
                uint32_t b0h[2] = {rvh[0], rvh[1]}, b1h[2] = {rvh[2], rvh[3]};
                uint32_t b0l[2] = {rvl[0], rvl[1]}, b1l[2] = {rvl[2], rvl[3]};
                MMA16816H(od[2*d0],   pa[kc2], b0h);
                MMA16816H(od[2*d0],   pa[kc2], b0l);
                MMA16816H(od[2*d0+1], pa[kc2], b1h);
                MMA16816H(od[2*d0+1], pa[kc2], b1l);
            }
        }

        __syncthreads();
        if (jt + 2 < njt) AT_ISSUE(jt + 2, st);
        else CP_COMMIT();          // keep group-count invariant for WAIT1
    }

    // ---- epilogue: O / l -> fp16 ----
    const float i0 = 1.0f / l0, i1 = 1.0f / l1;
    const long long row0 = (long long)(b*NS + q0 + w*16 + (lane >> 2)) * ND + h * HD;
    const long long row1 = row0 + 8ll * ND;
#pragma unroll
    for (int nd = 0; nd < 16; nd++) {
        const int d = nd*8 + (lane & 3)*2;
        *(uint32_t*)&of[row0 + d] = f16x2_pack(od[nd][0]*i0, od[nd][1]*i0);
        *(uint32_t*)&of[row1 + d] = f16x2_pack(od[nd][2]*i1, od[nd][3]*i1);
    }
#undef AT_ISSUE
}

// ============================================================================
extern "C" void kernel_launch(void* const* d_in, const int* in_sizes, int n_in,
                              void* d_out, int out_size)
{
    (void)in_sizes; (void)n_in; (void)out_size;
    const float* queries = (const float*)d_in[0];
    const float* keys    = (const float*)d_in[1];
    const float* values  = (const float*)d_in[2];
    const float* Wq = (const float*)d_in[3];
    const float* bq = (const float*)d_in[4];
    const float* Wk = (const float*)d_in[5];
    const float* bk = (const float*)d_in[6];
    const float* Wv = (const float*)d_in[7];
    const float* bv = (const float*)d_in[8];
    const float* Wo = (const float*)d_in[9];
    const float* bo = (const float*)d_in[10];
    float* out = (float*)d_out;

    float *q, *k;
    __half *whf, *af, *of, *qh, *ql, *kf, *vh, *vl;
    cudaGetSymbolAddress((void**)&q,   g_q);
    cudaGetSymbolAddress((void**)&k,   g_k);
    cudaGetSymbolAddress((void**)&whf, g_whf);
    cudaGetSymbolAddress((void**)&af,  g_af);
    cudaGetSymbolAddress((void**)&of,  g_of);
    cudaGetSymbolAddress((void**)&qh,  g_qh);
    cudaGetSymbolAddress((void**)&ql,  g_ql);
    cudaGetSymbolAddress((void**)&kf,  g_kf);
    cudaGetSymbolAddress((void**)&vh,  g_vh);
    cudaGetSymbolAddress((void**)&vl,  g_vl);

    cudaFuncSetAttribute(gemm_f16_kernel,
                         cudaFuncAttributeMaxDynamicSharedMemorySize, GF_SMEM);
    cudaFuncSetAttribute(attn_mma_kernel,
                         cudaFuncAttributeMaxDynamicSharedMemorySize, AT_SMEM);

    // ---- transpose + fp16-convert weights ----
    const float* Ws[4] = {Wq, Wk, Wv, Wo};
    dim3 gw(ND/32, ND/32), bw(32, 8);
    for (int i = 0; i < 4; i++)
        conv_w_kernel<<<gw, bw>>>(Ws[i], whf + (long long)i*ND*ND);

    const int nconv = NM*ND/8/256;
    dim3 gtg(ND/128, NM/128);                  // (16, 32)

    // ---- projections (1-pass fp16) ----
    conv_a_kernel<<<nconv, 256>>>(queries, af);
    gemm_f16_kernel<<<gtg, 256, GF_SMEM>>>(af, whf + 0ll*ND*ND, bq, q, nullptr, nullptr);
    conv_a_kernel<<<nconv, 256>>>(keys, af);
    gemm_f16_kernel<<<gtg, 256, GF_SMEM>>>(af, whf + 1ll*ND*ND, bk, k, nullptr, nullptr);
    conv_a_kernel<<<nconv, 256>>>(values, af);
    gemm_f16_kernel<<<gtg, 256, GF_SMEM>>>(af, whf + 2ll*ND*ND, bv, nullptr, vh, vl);

    // ---- RoPE: Q 2-limb fp16 (scaled), K single fp16 ----
    int nrope = NM * NH * 64;
    rope2f_kernel<<<nrope/256, 256>>>(q, qh, ql, 0.08838834764831845f);
    rope1f_kernel<<<nrope/256, 256>>>(k, kf);

    // ---- attention (fp16 2-pass; writes fp16 O) ----
    dim3 ga(NS/128, NH, NB);
    attn_mma_kernel<<<ga, 256, AT_SMEM>>>(qh, ql, kf, vh, vl, of);

    // ---- output projection (1-pass fp16) ----
    gemm_f16_kernel<<<gtg, 256, GF_SMEM>>>(of, whf + 3ll*ND*ND, bo, out, nullptr, nullptr);
}

// round 12
// speedup vs baseline: 4.3450x; 1.1351x over previous
#include <cuda_runtime.h>
#include <cuda_bf16.h>
#include <cuda_fp16.h>
#include <cstdint>
#include <math.h>

#define NB 2
#define NS 2048
#define ND 2048
#define NH 16
#define HD 128
#define NM (NB*NS)   // 4096 rows

// ---- scratch (static device arrays; no allocation allowed) ----
__device__ float g_q[NM*ND];                 // fp32 Q proj (pre-rope)
__device__ float g_k[NM*ND];                 // fp32 K proj
__device__ __half g_whf[4ll*ND*ND];          // W^T fp16 single, [N][K] K-major
__device__ __half g_af[(long long)NM*ND];    // activation fp16 (gemm A)
__device__ __half g_of[(long long)NM*ND];    // attention O fp16
__device__ __half g_qf[(long long)NM*ND];    // roped Q fp16 (scaled)
__device__ __half g_kf[(long long)NM*ND];    // roped K fp16
__device__ __half g_vf[(long long)NM*ND];    // V proj fp16

__device__ __forceinline__ uint32_t smem_u32(const void* p) {
    uint32_t a;
    asm("{ .reg .u64 t; cvta.to.shared.u64 t, %1; cvt.u32.u64 %0, t; }"
        : "=r"(a) : "l"(p));
    return a;
}

// ---- base-target tensor core primitives (sm_80-class, valid on compute_103) ----
#define LDSM4(r, addr) \
    asm volatile("ldmatrix.sync.aligned.m8n8.x4.shared.b16 {%0,%1,%2,%3}, [%4];" \
        : "=r"((r)[0]), "=r"((r)[1]), "=r"((r)[2]), "=r"((r)[3]) : "r"(addr))

#define LDSM4T(r, addr) \
    asm volatile("ldmatrix.sync.aligned.m8n8.x4.trans.shared.b16 {%0,%1,%2,%3}, [%4];" \
        : "=r"((r)[0]), "=r"((r)[1]), "=r"((r)[2]), "=r"((r)[3]) : "r"(addr))

#define MMA16816H(d, a, b) \
    asm volatile("mma.sync.aligned.m16n8k16.row.col.f32.f16.f16.f32 " \
        "{%0,%1,%2,%3}, {%4,%5,%6,%7}, {%8,%9}, {%0,%1,%2,%3};" \
        : "+f"((d)[0]), "+f"((d)[1]), "+f"((d)[2]), "+f"((d)[3]) \
        : "r"((a)[0]), "r"((a)[1]), "r"((a)[2]), "r"((a)[3]), \
          "r"((b)[0]), "r"((b)[1]))

#define CP_ASYNC16(dst, src) \
    asm volatile("cp.async.cg.shared.global [%0], [%1], 16;" \
                 :: "r"(dst), "l"(src) : "memory")
#define CP_COMMIT()  asm volatile("cp.async.commit_group;" ::: "memory")
#define CP_WAIT1()   asm volatile("cp.async.wait_group 1;" ::: "memory")
#define CP_WAIT0()   asm volatile("cp.async.wait_group 0;" ::: "memory")

__device__ __forceinline__ uint32_t f16x2_pack(float lo, float hi) {
    __half2 v = __floats2half2_rn(lo, hi);
    return *reinterpret_cast<uint32_t*>(&v);
}

// ============================================================================
// conv_a: fp32 -> fp16 single (8 elems/thread)
// ============================================================================
__global__ void conv_a_kernel(const float* __restrict__ X, __half* __restrict__ Y)
{
    long long idx = (long long)(blockIdx.x * blockDim.x + threadIdx.x) * 8;
    float4 a = *(const float4*)(X + idx);
    float4 b = *(const float4*)(X + idx + 4);
    uint4 o;
    o.x = f16x2_pack(a.x, a.y);
    o.y = f16x2_pack(a.z, a.w);
    o.z = f16x2_pack(b.x, b.y);
    o.w = f16x2_pack(b.z, b.w);
    *(uint4*)(Y + idx) = o;
}

// ============================================================================
// conv_w: W[K][N] fp32 -> W^T fp16 single [N][K] (transpose)
// ============================================================================
__global__ void conv_w_kernel(const float* __restrict__ W, __half* __restrict__ Wt)
{
    __shared__ float t[32][33];
    int n0 = blockIdx.x * 32, k0 = blockIdx.y * 32;
    int tx = threadIdx.x, ty = threadIdx.y;
    for (int r = ty; r < 32; r += 8)
        t[r][tx] = W[(long long)(k0 + r) * ND + n0 + tx];
    __syncthreads();
    for (int r = ty; r < 32; r += 8)
        Wt[(long long)(n0 + r) * ND + k0 + tx] = __float2half_rn(t[tx][r]);
}

// ============================================================================
// 1-pass fp16 GEMM on mma.sync: C = A(f16) @ W^T(f16) + bias
// Outputs fp32 C and/or fp16 single Cf.
// CTA 128x128, 8 warps (warp tile 64x32), K-chunk 32 f16, double buffer.
// smem rows: 64B payload, 80B stride (conflict-free ldmatrix).
// ============================================================================
#define GF_STAGE 20480                    // 2 matrices * 128 rows * 80B
#define GF_SMEM  (2*GF_STAGE)             // 40960

__global__ __launch_bounds__(256)
void gemm_f16_kernel(const __half* __restrict__ Af,
                     const __half* __restrict__ Wf,
                     const float* __restrict__ bias,
                     float* __restrict__ C,
                     __half* __restrict__ Cf)
{
    extern __shared__ char dsm[];
    const uint32_t sb = smem_u32(dsm);
    const int tid  = threadIdx.x;
    const int lane = tid & 31, wid = tid >> 5;
    const int wm = wid & 1, wn = wid >> 1;      // warp tile: m 64, n 32
    const int m0 = blockIdx.y * 128, n0 = blockIdx.x * 128;

    const int lrow = tid >> 1;
    const int lc   = (tid & 1) * 16;            // elements (32B)
    const __half* gsrc[2];
    gsrc[0] = Af + (long long)(m0 + lrow) * ND + lc;
    gsrc[1] = Wf + (long long)(n0 + lrow) * ND + lc;
    const uint32_t sdst0 = sb + lrow * 80 + (tid & 1) * 32;

    float acc[4][4][4];
#pragma unroll
    for (int i = 0; i < 4; i++)
#pragma unroll
        for (int j = 0; j < 4; j++)
#pragma unroll
            for (int c = 0; c < 4; c++) acc[i][j][c] = 0.0f;

#define GF_ISSUE(ch, stage) do { \
        uint32_t s0 = sdst0 + (stage) * GF_STAGE; \
        _Pragma("unroll") \
        for (int m = 0; m < 2; m++) { \
            const __half* g = gsrc[m] + (ch) * 32; \
            uint32_t d = s0 + m * 10240; \
            CP_ASYNC16(d, g); \
            CP_ASYNC16(d + 16, g + 8); \
        } \
        CP_COMMIT(); \
    } while (0)

    GF_ISSUE(0, 0);
    GF_ISSUE(1, 1);

    for (int ch = 0; ch < 64; ch++) {
        const int st = ch & 1;
        CP_WAIT1();
        __syncthreads();
        const uint32_t abase = sb + st * GF_STAGE + (wm * 64) * 80
                             + (lane & 15) * 80 + (lane >> 4) * 16;
        const uint32_t bbase = sb + st * GF_STAGE + 10240 + (wn * 32) * 80
                             + (lane & 15) * 80 + (lane >> 4) * 16;
#pragma unroll
        for (int kk = 0; kk < 2; kk++) {        // two k16 steps per 32-elem chunk
            uint32_t bh[4][2];
#pragma unroll
            for (int np = 0; np < 2; np++) {
                uint32_t r[4];
                LDSM4(r, bbase + np * 1280 + kk * 32);
                bh[np*2+0][0] = r[0]; bh[np*2+0][1] = r[2];
                bh[np*2+1][0] = r[1]; bh[np*2+1][1] = r[3];
            }
#pragma unroll
            for (int mt = 0; mt < 4; mt++) {
                uint32_t af[4];
                LDSM4(af, abase + mt * 1280 + kk * 32);
#pragma unroll
                for (int nt = 0; nt < 4; nt++)
                    MMA16816H(acc[mt][nt], af, bh[nt]);
            }
        }
        __syncthreads();
        if (ch + 2 < 64) GF_ISSUE(ch + 2, st);
        else CP_COMMIT();          // keep group-count invariant for WAIT1
    }

    // ---- epilogue ----
    const int r0 = m0 + wm * 64 + (lane >> 2);
    const int c0 = n0 + wn * 32 + (lane & 3) * 2;
#pragma unroll
    for (int nt = 0; nt < 4; nt++) {
        const int c = c0 + nt * 8;
        const float b0 = bias[c], b1 = bias[c + 1];
#pragma unroll
        for (int mt = 0; mt < 4; mt++) {
            const int r = r0 + mt * 16;
            float v00 = acc[mt][nt][0] + b0, v01 = acc[mt][nt][1] + b1;
            float v10 = acc[mt][nt][2] + b0, v11 = acc[mt][nt][3] + b1;
            if (C) {
                *(float2*)&C[(long long)r * ND + c]       = make_float2(v00, v01);
                *(float2*)&C[(long long)(r + 8) * ND + c] = make_float2(v10, v11);
            }
            if (Cf) {
                *(uint32_t*)&Cf[(long long)r * ND + c]       = f16x2_pack(v00, v01);
                *(uint32_t*)&Cf[(long long)(r + 8) * ND + c] = f16x2_pack(v10, v11);
            }
        }
    }
#undef GF_ISSUE
}

// ============================================================================
// RoPE: fp32 proj -> rotated single fp16 (optional scale folded in)
// ============================================================================
__global__ void rope1f_kernel(const float* __restrict__ X, __half* __restrict__ Y,
                              float scale)
{
    int idx = blockIdx.x * blockDim.x + threadIdx.x;  // NM * NH * 64
    int i   = idx & 63;
    int h   = (idx >> 6) & (NH - 1);
    int row = idx >> 10;
    int s   = row & (NS - 1);
    float invf = powf(10000.0f, -(float)i / 64.0f);
    float ang = (float)s * invf;
    float sn, cs;
    sincosf(ang, &sn, &cs);
    long long off = (long long)row * ND + h * HD + i;
    float x1 = X[off], x2 = X[off + 64];
    Y[off]      = __float2half_rn((x1 * cs - x2 * sn) * scale);
    Y[off + 64] = __float2half_rn((x2 * cs + x1 * sn) * scale);
}

// ============================================================================
// Causal flash attention on mma.sync, fully 1-pass fp16:
//   S = Q x K^T    (1 MMA pass)
//   O += P x V     (1 MMA pass)
// CTA: (b, h, 128-q tile); 8 warps. K/V stage = 2 tiles, double buffered.
// Output single fp16 (feeds the 1-pass output projection).
// ============================================================================
#define AT_RS    272                       // row stride bytes (136 fp16)
#define AT_TSIZE (64*AT_RS)                // 17408 per matrix tile
#define AT_STAGE (2*AT_TSIZE)              // 34816: K, V
#define AT_SMEM  (2*AT_STAGE)              // 69632

__global__ __launch_bounds__(256)
void attn_mma_kernel(const __half* __restrict__ qf,
                     const __half* __restrict__ kf,
                     const __half* __restrict__ vf,
                     __half* __restrict__ of)
{
    extern __shared__ char dsm[];
    const uint32_t sb = smem_u32(dsm);
    const int tid  = threadIdx.x;
    const int lane = tid & 31, w = tid >> 5;
    const int qt = (NS/128 - 1) - blockIdx.x;   // heavy tiles first
    const int h  = blockIdx.y;
    const int b  = blockIdx.z;
    const int q0 = qt * 128;
    const long long gbase = (long long)b * NS * ND + h * HD;

    // ---- stage Q (128 rows) into stage-0 region; consumed to regs ----
    {
        int r = tid & 127;
        const __half* src = qf + gbase + (long long)(q0 + r) * ND + (tid >> 7) * 64;
        uint32_t dst = sb + r * AT_RS + (tid >> 7) * 128;
#pragma unroll
        for (int c = 0; c < 8; c++) CP_ASYNC16(dst + c*16, src + c*8);
        CP_COMMIT();
        CP_WAIT0();
        __syncthreads();
    }

    // ---- Q fragments to registers (8 k16-chunks) ----
    uint32_t qfr[8][4];
    {
        uint32_t qaddr = sb + (w*16 + (lane & 15)) * AT_RS + (lane >> 4) * 16;
#pragma unroll
        for (int kc = 0; kc < 8; kc++)
            LDSM4(qfr[kc], qaddr + kc*32);
    }
    __syncthreads();   // done reading Q staging region

    // ---- K/V tile loader: 2 matrices x 64 rows, threads 0..127 ----
    const __half* kvsrc = nullptr;
    uint32_t kvdst = 0;
    const bool loader = (tid < 128);
    if (loader) {
        kvsrc = ((tid < 64) ? kf : vf) + gbase + (long long)(tid & 63) * ND;
        kvdst = sb + (tid >> 6) * AT_TSIZE + (tid & 63) * AT_RS;
    }

#define AT_ISSUE(jt, st) do { \
        if (loader) { \
            const __half* g = kvsrc + (long long)(jt) * 64 * ND; \
            uint32_t d = kvdst + (st) * AT_STAGE; \
            _Pragma("unroll") \
            for (int c = 0; c < 16; c++) CP_ASYNC16(d + c*16, g + c*8); \
        } \
        CP_COMMIT(); \
    } while (0)

    const int njt = 2*qt + 2;
    AT_ISSUE(0, 0);
    AT_ISSUE(1, 1);

    float m0v = -1e30f, m1v = -1e30f, l0 = 0.0f, l1 = 0.0f;
    float od[16][4];
#pragma unroll
    for (int nd = 0; nd < 16; nd++)
#pragma unroll
        for (int c = 0; c < 4; c++) od[nd][c] = 0.0f;

    for (int jt = 0; jt < njt; jt++) {
        const int st = jt & 1;
        CP_WAIT1();
        __syncthreads();
        const uint32_t kbase = sb + st * AT_STAGE;
        const uint32_t vbase = kbase + AT_TSIZE;

        // ---- S = Q·K^T (16 x 64 per warp), 1 pass ----
        float sc[8][4];
#pragma unroll
        for (int n = 0; n < 8; n++)
#pragma unroll
            for (int c = 0; c < 4; c++) sc[n][c] = 0.0f;

#pragma unroll
        for (int kc = 0; kc < 8; kc++) {
#pragma unroll
            for (int ng = 0; ng < 4; ng++) {
                uint32_t rk[4];
                LDSM4(rk, kbase + (ng*16 + (lane & 15)) * AT_RS
                          + kc*32 + (lane >> 4) * 16);
                uint32_t b0[2] = {rk[0], rk[2]}, b1[2] = {rk[1], rk[3]};
                MMA16816H(sc[2*ng],   qfr[kc], b0);
                MMA16816H(sc[2*ng+1], qfr[kc], b1);
            }
        }

        // ---- causal mask (only the two diagonal k-tiles) ----
        if (jt >= njt - 2) {
            const int qrow = q0 + w*16 + (lane >> 2);
            const int kc0  = jt*64 + (lane & 3)*2;
#pragma unroll
            for (int n = 0; n < 8; n++) {
                int kcol = kc0 + n*8;
                if (kcol     > qrow)     sc[n][0] = -1e30f;
                if (kcol + 1 > qrow)     sc[n][1] = -1e30f;
                if (kcol     > qrow + 8) sc[n][2] = -1e30f;
                if (kcol + 1 > qrow + 8) sc[n][3] = -1e30f;
            }
        }

        // ---- online softmax ----
        float mx0 = -1e30f, mx1 = -1e30f;
#pragma unroll
        for (int n = 0; n < 8; n++) {
            mx0 = fmaxf(mx0, fmaxf(sc[n][0], sc[n][1]));
            mx1 = fmaxf(mx1, fmaxf(sc[n][2], sc[n][3]));
        }
        mx0 = fmaxf(mx0, __shfl_xor_sync(0xffffffffu, mx0, 1));
        mx0 = fmaxf(mx0, __shfl_xor_sync(0xffffffffu, mx0, 2));
        mx1 = fmaxf(mx1, __shfl_xor_sync(0xffffffffu, mx1, 1));
        mx1 = fmaxf(mx1, __shfl_xor_sync(0xffffffffu, mx1, 2));
        float mn0 = fmaxf(m0v, mx0), mn1 = fmaxf(m1v, mx1);
        float corr0 = __expf(m0v - mn0), corr1 = __expf(m1v - mn1);
        float ps0 = 0.0f, ps1 = 0.0f;
#pragma unroll
        for (int n = 0; n < 8; n++) {
            sc[n][0] = __expf(sc[n][0] - mn0);
            sc[n][1] = __expf(sc[n][1] - mn0);
            sc[n][2] = __expf(sc[n][2] - mn1);
            sc[n][3] = __expf(sc[n][3] - mn1);
            ps0 += sc[n][0] + sc[n][1];
            ps1 += sc[n][2] + sc[n][3];
        }
        ps0 += __shfl_xor_sync(0xffffffffu, ps0, 1);
        ps0 += __shfl_xor_sync(0xffffffffu, ps0, 2);
        ps1 += __shfl_xor_sync(0xffffffffu, ps1, 1);
        ps1 += __shfl_xor_sync(0xffffffffu, ps1, 2);
        l0 = l0 * corr0 + ps0;  m0v = mn0;
        l1 = l1 * corr1 + ps1;  m1v = mn1;
#pragma unroll
        for (int nd = 0; nd < 16; nd++) {
            od[nd][0] *= corr0; od[nd][1] *= corr0;
            od[nd][2] *= corr1; od[nd][3] *= corr1;
        }

        // ---- repack P (C-frags) into single-fp16 A-frags ----
        uint32_t pa[4][4];
#pragma unroll
        for (int kc2 = 0; kc2 < 4; kc2++) {
            const int n0i = 2*kc2, n1i = 2*kc2 + 1;
            pa[kc2][0] = f16x2_pack(sc[n0i][0], sc[n0i][1]);
            pa[kc2][1] = f16x2_pack(sc[n0i][2], sc[n0i][3]);
            pa[kc2][2] = f16x2_pack(sc[n1i][0], sc[n1i][1]);
            pa[kc2][3] = f16x2_pack(sc[n1i][2], sc[n1i][3]);
        }

        // ---- O += P·V, 1 pass ----
#pragma unroll
        for (int d0 = 0; d0 < 8; d0++) {
#pragma unroll
            for (int kc2 = 0; kc2 < 4; kc2++) {
                uint32_t rv[4];
                LDSM4T(rv, vbase + (kc2*16 + (lane & 15)) * AT_RS
                           + d0*32 + (lane >> 4) * 16);
                uint32_t b0[2] = {rv[0], rv[1]}, b1[2] = {rv[2], rv[3]};
                MMA16816H(od[2*d0],   pa[kc2], b0);
                MMA16816H(od[2*d0+1], pa[kc2], b1);
            }
        }

        __syncthreads();
        if (jt + 2 < njt) AT_ISSUE(jt + 2, st);
        else CP_COMMIT();          // keep group-count invariant for WAIT1
    }

    // ---- epilogue: O / l -> fp16 ----
    const float i0 = 1.0f / l0, i1 = 1.0f / l1;
    const long long row0 = (long long)(b*NS + q0 + w*16 + (lane >> 2)) * ND + h * HD;
    const long long row1 = row0 + 8ll * ND;
#pragma unroll
    for (int nd = 0; nd < 16; nd++) {
        const int d = nd*8 + (lane & 3)*2;
        *(uint32_t*)&of[row0 + d] = f16x2_pack(od[nd][0]*i0, od[nd][1]*i0);
        *(uint32_t*)&of[row1 + d] = f16x2_pack(od[nd][2]*i1, od[nd][3]*i1);
    }
#undef AT_ISSUE
}

// ============================================================================
extern "C" void kernel_launch(void* const* d_in, const int* in_sizes, int n_in,
                              void* d_out, int out_size)
{
    (void)in_sizes; (void)n_in; (void)out_size;
    const float* queries = (const float*)d_in[0];
    const float* keys    = (const float*)d_in[1];
    const float* values  = (const float*)d_in[2];
    const float* Wq = (const float*)d_in[3];
    const float* bq = (const float*)d_in[4];
    const float* Wk = (const float*)d_in[5];
    const float* bk = (const float*)d_in[6];
    const float* Wv = (const float*)d_in[7];
    const float* bv = (const float*)d_in[8];
    const float* Wo = (const float*)d_in[9];
    const float* bo = (const float*)d_in[10];
    float* out = (float*)d_out;

    float *q, *k;
    __half *whf, *af, *of, *qf, *kf, *vf;
    cudaGetSymbolAddress((void**)&q,   g_q);
    cudaGetSymbolAddress((void**)&k,   g_k);
    cudaGetSymbolAddress((void**)&whf, g_whf);
    cudaGetSymbolAddress((void**)&af,  g_af);
    cudaGetSymbolAddress((void**)&of,  g_of);
    cudaGetSymbolAddress((void**)&qf,  g_qf);
    cudaGetSymbolAddress((void**)&kf,  g_kf);
    cudaGetSymbolAddress((void**)&vf,  g_vf);

    cudaFuncSetAttribute(gemm_f16_kernel,
                         cudaFuncAttributeMaxDynamicSharedMemorySize, GF_SMEM);
    cudaFuncSetAttribute(attn_mma_kernel,
                         cudaFuncAttributeMaxDynamicSharedMemorySize, AT_SMEM);

    // ---- transpose + fp16-convert weights ----
    const float* Ws[4] = {Wq, Wk, Wv, Wo};
    dim3 gw(ND/32, ND/32), bw(32, 8);
    for (int i = 0; i < 4; i++)
        conv_w_kernel<<<gw, bw>>>(Ws[i], whf + (long long)i*ND*ND);

    const int nconv = NM*ND/8/256;
    dim3 gtg(ND/128, NM/128);                  // (16, 32)

    // ---- projections (1-pass fp16) ----
    conv_a_kernel<<<nconv, 256>>>(queries, af);
    gemm_f16_kernel<<<gtg, 256, GF_SMEM>>>(af, whf + 0ll*ND*ND, bq, q, nullptr);
    conv_a_kernel<<<nconv, 256>>>(keys, af);
    gemm_f16_kernel<<<gtg, 256, GF_SMEM>>>(af, whf + 1ll*ND*ND, bk, k, nullptr);
    conv_a_kernel<<<nconv, 256>>>(values, af);
    gemm_f16_kernel<<<gtg, 256, GF_SMEM>>>(af, whf + 2ll*ND*ND, bv, nullptr, vf);

    // ---- RoPE: single fp16 (scale folded into Q) ----
    int nrope = NM * NH * 64;
    rope1f_kernel<<<nrope/256, 256>>>(q, qf, 0.08838834764831845f);
    rope1f_kernel<<<nrope/256, 256>>>(k, kf, 1.0f);

    // ---- attention (fully 1-pass fp16) ----
    dim3 ga(NS/128, NH, NB);
    attn_mma_kernel<<<ga, 256, AT_SMEM>>>(qf, kf, vf, of);

    // ---- output projection (1-pass fp16) ----
    gemm_f16_kernel<<<gtg, 256, GF_SMEM>>>(of, whf + 3ll*ND*ND, bo, out, nullptr);
}

// round 13
// speedup vs baseline: 4.6320x; 1.0661x over previous
#include <cuda_runtime.h>
#include <cuda_bf16.h>
#include <cuda_fp16.h>
#include <cstdint>
#include <math.h>

#define NB 2
#define NS 2048
#define ND 2048
#define NH 16
#define HD 128
#define NM (NB*NS)   // 4096 rows

// ---- scratch (static device arrays; no allocation allowed) ----
__device__ float g_q[NM*ND];                     // fp32 Q proj (pre-rope)
__device__ float g_k[NM*ND];                     // fp32 K proj
__device__ __half g_whf[4ll*ND*ND];              // W^T fp16, [N][K] K-major
__device__ __half g_af[3ll*NM*ND];               // fp16 activations (q,k,v inputs)
__device__ __half g_of[(long long)NM*ND];        // attention O fp16
__device__ __half g_qf[(long long)NM*ND];        // roped Q fp16 (scaled)
__device__ __half g_kf[(long long)NM*ND];        // roped K fp16
__device__ __half g_vf[(long long)NM*ND];        // V proj fp16

__device__ __forceinline__ uint32_t smem_u32(const void* p) {
    uint32_t a;
    asm("{ .reg .u64 t; cvta.to.shared.u64 t, %1; cvt.u32.u64 %0, t; }"
        : "=r"(a) : "l"(p));
    return a;
}

// ---- base-target tensor core primitives (sm_80-class, valid on compute_103) ----
#define LDSM4(r, addr) \
    asm volatile("ldmatrix.sync.aligned.m8n8.x4.shared.b16 {%0,%1,%2,%3}, [%4];" \
        : "=r"((r)[0]), "=r"((r)[1]), "=r"((r)[2]), "=r"((r)[3]) : "r"(addr))

#define LDSM4T(r, addr) \
    asm volatile("ldmatrix.sync.aligned.m8n8.x4.trans.shared.b16 {%0,%1,%2,%3}, [%4];" \
        : "=r"((r)[0]), "=r"((r)[1]), "=r"((r)[2]), "=r"((r)[3]) : "r"(addr))

#define MMA16816H(d, a, b) \
    asm volatile("mma.sync.aligned.m16n8k16.row.col.f32.f16.f16.f32 " \
        "{%0,%1,%2,%3}, {%4,%5,%6,%7}, {%8,%9}, {%0,%1,%2,%3};" \
        : "+f"((d)[0]), "+f"((d)[1]), "+f"((d)[2]), "+f"((d)[3]) \
        : "r"((a)[0]), "r"((a)[1]), "r"((a)[2]), "r"((a)[3]), \
          "r"((b)[0]), "r"((b)[1]))

#define CP_ASYNC16(dst, src) \
    asm volatile("cp.async.cg.shared.global [%0], [%1], 16;" \
                 :: "r"(dst), "l"(src) : "memory")
#define CP_COMMIT()  asm volatile("cp.async.commit_group;" ::: "memory")
#define CP_WAIT1()   asm volatile("cp.async.wait_group 1;" ::: "memory")
#define CP_WAIT0()   asm volatile("cp.async.wait_group 0;" ::: "memory")

__device__ __forceinline__ uint32_t f16x2_pack(float lo, float hi) {
    __half2 v = __floats2half2_rn(lo, hi);
    return *reinterpret_cast<uint32_t*>(&v);
}

// ============================================================================
// conv_a_all: fp32 -> fp16 for queries/keys/values in one launch (z selects)
// ============================================================================
__global__ void conv_a_all_kernel(const float* __restrict__ Xq,
                                  const float* __restrict__ Xk,
                                  const float* __restrict__ Xv,
                                  __half* __restrict__ Y)
{
    const float* X = (blockIdx.z == 0) ? Xq : (blockIdx.z == 1) ? Xk : Xv;
    __half* Yz = Y + (long long)blockIdx.z * NM * ND;
    long long idx = (long long)(blockIdx.x * blockDim.x + threadIdx.x) * 8;
    float4 a = *(const float4*)(X + idx);
    float4 b = *(const float4*)(X + idx + 4);
    uint4 o;
    o.x = f16x2_pack(a.x, a.y);
    o.y = f16x2_pack(a.z, a.w);
    o.z = f16x2_pack(b.x, b.y);
    o.w = f16x2_pack(b.z, b.w);
    *(uint4*)(Yz + idx) = o;
}

// ============================================================================
// conv_w_all: 4 weight matrices, one launch (z selects). Transpose to [N][K].
// ============================================================================
__global__ void conv_w_all_kernel(const float* __restrict__ W0,
                                  const float* __restrict__ W1,
                                  const float* __restrict__ W2,
                                  const float* __restrict__ W3,
                                  __half* __restrict__ Wt)
{
    const float* Wz = (blockIdx.z == 0) ? W0 : (blockIdx.z == 1) ? W1
                    : (blockIdx.z == 2) ? W2 : W3;
    __half* Wtz = Wt + (long long)blockIdx.z * ND * ND;
    __shared__ float t[32][33];
    int n0 = blockIdx.x * 32, k0 = blockIdx.y * 32;
    int tx = threadIdx.x, ty = threadIdx.y;
    for (int r = ty; r < 32; r += 8)
        t[r][tx] = Wz[(long long)(k0 + r) * ND + n0 + tx];
    __syncthreads();
    for (int r = ty; r < 32; r += 8)
        Wtz[(long long)(n0 + r) * ND + k0 + tx] = __float2half_rn(t[tx][r]);
}

// ============================================================================
// 1-pass fp16 GEMM (device function): C = A(f16) @ W^T(f16) + bias
// Outputs fp32 C and/or fp16 single Cf.
// CTA 128x128, 8 warps (warp tile 64x32), K-chunk 32 f16, double buffer.
// smem rows: 64B payload, 80B stride (conflict-free ldmatrix).
// ============================================================================
#define GF_STAGE 20480                    // 2 matrices * 128 rows * 80B
#define GF_SMEM  (2*GF_STAGE)             // 40960

__device__ __forceinline__
void gemm_f16_body(char* dsm,
                   const __half* __restrict__ Af,
                   const __half* __restrict__ Wf,
                   const float* __restrict__ bias,
                   float* __restrict__ C,
                   __half* __restrict__ Cf,
                   int m0, int n0)
{
    const uint32_t sb = smem_u32(dsm);
    const int tid  = threadIdx.x;
    const int lane = tid & 31, wid = tid >> 5;
    const int wm = wid & 1, wn = wid >> 1;      // warp tile: m 64, n 32

    const int lrow = tid >> 1;
    const int lc   = (tid & 1) * 16;            // elements (32B)
    const __half* gsrc[2];
    gsrc[0] = Af + (long long)(m0 + lrow) * ND + lc;
    gsrc[1] = Wf + (long long)(n0 + lrow) * ND + lc;
    const uint32_t sdst0 = sb + lrow * 80 + (tid & 1) * 32;

    float acc[4][4][4];
#pragma unroll
    for (int i = 0; i < 4; i++)
#pragma unroll
        for (int j = 0; j < 4; j++)
#pragma unroll
            for (int c = 0; c < 4; c++) acc[i][j][c] = 0.0f;

#define GF_ISSUE(ch, stage) do { \
        uint32_t s0 = sdst0 + (stage) * GF_STAGE; \
        _Pragma("unroll") \
        for (int m = 0; m < 2; m++) { \
            const __half* g = gsrc[m] + (ch) * 32; \
            uint32_t d = s0 + m * 10240; \
            CP_ASYNC16(d, g); \
            CP_ASYNC16(d + 16, g + 8); \
        } \
        CP_COMMIT(); \
    } while (0)

    GF_ISSUE(0, 0);
    GF_ISSUE(1, 1);

    for (int ch = 0; ch < 64; ch++) {
        const int st = ch & 1;
        CP_WAIT1();
        __syncthreads();
        const uint32_t abase = sb + st * GF_STAGE + (wm * 64) * 80
                             + (lane & 15) * 80 + (lane >> 4) * 16;
        const uint32_t bbase = sb + st * GF_STAGE + 10240 + (wn * 32) * 80
                             + (lane & 15) * 80 + (lane >> 4) * 16;
#pragma unroll
        for (int kk = 0; kk < 2; kk++) {        // two k16 steps per 32-elem chunk
            uint32_t bh[4][2];
#pragma unroll
            for (int np = 0; np < 2; np++) {
                uint32_t r[4];
                LDSM4(r, bbase + np * 1280 + kk * 32);
                bh[np*2+0][0] = r[0]; bh[np*2+0][1] = r[2];
                bh[np*2+1][0] = r[1]; bh[np*2+1][1] = r[3];
            }
#pragma unroll
            for (int mt = 0; mt < 4; mt++) {
                uint32_t af[4];
                LDSM4(af, abase + mt * 1280 + kk * 32);
#pragma unroll
                for (int nt = 0; nt < 4; nt++)
                    MMA16816H(acc[mt][nt], af, bh[nt]);
            }
        }
        __syncthreads();
        if (ch + 2 < 64) GF_ISSUE(ch + 2, st);
        else CP_COMMIT();          // keep group-count invariant for WAIT1
    }

    // ---- epilogue ----
    const int r0 = m0 + wm * 64 + (lane >> 2);
    const int c0 = n0 + wn * 32 + (lane & 3) * 2;
#pragma unroll
    for (int nt = 0; nt < 4; nt++) {
        const int c = c0 + nt * 8;
        const float b0 = bias[c], b1 = bias[c + 1];
#pragma unroll
        for (int mt = 0; mt < 4; mt++) {
            const int r = r0 + mt * 16;
            float v00 = acc[mt][nt][0] + b0, v01 = acc[mt][nt][1] + b1;
            float v10 = acc[mt][nt][2] + b0, v11 = acc[mt][nt][3] + b1;
            if (C) {
                *(float2*)&C[(long long)r * ND + c]       = make_float2(v00, v01);
                *(float2*)&C[(long long)(r + 8) * ND + c] = make_float2(v10, v11);
            }
            if (Cf) {
                *(uint32_t*)&Cf[(long long)r * ND + c]       = f16x2_pack(v00, v01);
                *(uint32_t*)&Cf[(long long)(r + 8) * ND + c] = f16x2_pack(v10, v11);
            }
        }
    }
#undef GF_ISSUE
}

// ---- merged Q/K/V projection: gridDim.z = 3 selects matrix ----
__global__ __launch_bounds__(256, 2)
void gemm_qkv_kernel(const __half* __restrict__ af,
                     const __half* __restrict__ whf,
                     const float* __restrict__ bq,
                     const float* __restrict__ bk,
                     const float* __restrict__ bv,
                     float* __restrict__ q, float* __restrict__ k,
                     __half* __restrict__ vf)
{
    extern __shared__ char dsm[];
    const int z = blockIdx.z;
    const __half* Af = af + (long long)z * NM * ND;
    const __half* Wf = whf + (long long)z * ND * ND;
    const float* bias = (z == 0) ? bq : (z == 1) ? bk : bv;
    float* C   = (z == 0) ? q : (z == 1) ? k : nullptr;
    __half* Cf = (z == 2) ? vf : nullptr;
    gemm_f16_body(dsm, Af, Wf, bias, C, Cf,
                  blockIdx.y * 128, blockIdx.x * 128);
}

// ---- single GEMM (output projection) ----
__global__ __launch_bounds__(256, 2)
void gemm_f16_kernel(const __half* __restrict__ Af,
                     const __half* __restrict__ Wf,
                     const float* __restrict__ bias,
                     float* __restrict__ C,
                     __half* __restrict__ Cf)
{
    extern __shared__ char dsm[];
    gemm_f16_body(dsm, Af, Wf, bias, C, Cf,
                  blockIdx.y * 128, blockIdx.x * 128);
}

// ============================================================================
// rope_all: Q (z=0, scaled) and K (z=1) in one launch
// ============================================================================
__global__ void rope_all_kernel(const float* __restrict__ Q,
                                const float* __restrict__ K,
                                __half* __restrict__ Qo,
                                __half* __restrict__ Ko)
{
    const float* X = blockIdx.z ? K : Q;
    __half* Y = blockIdx.z ? Ko : Qo;
    const float scale = blockIdx.z ? 1.0f : 0.08838834764831845f;
    int idx = blockIdx.x * blockDim.x + threadIdx.x;  // NM * NH * 64
    int i   = idx & 63;
    int h   = (idx >> 6) & (NH - 1);
    int row = idx >> 10;
    int s   = row & (NS - 1);
    float invf = powf(10000.0f, -(float)i / 64.0f);
    float ang = (float)s * invf;
    float sn, cs;
    sincosf(ang, &sn, &cs);
    long long off = (long long)row * ND + h * HD + i;
    float x1 = X[off], x2 = X[off + 64];
    Y[off]      = __float2half_rn((x1 * cs - x2 * sn) * scale);
    Y[off + 64] = __float2half_rn((x2 * cs + x1 * sn) * scale);
}

// ============================================================================
// Causal flash attention on mma.sync, fully 1-pass fp16:
//   S = Q x K^T    (1 MMA pass);  O += P x V  (1 MMA pass)
// CTA: (b, h, 128-q tile); 8 warps. K/V stage = 2 tiles, double buffered.
// ============================================================================
#define AT_RS    272                       // row stride bytes (136 fp16)
#define AT_TSIZE (64*AT_RS)                // 17408 per matrix tile
#define AT_STAGE (2*AT_TSIZE)              // 34816: K, V
#define AT_SMEM  (2*AT_STAGE)              // 69632

__global__ __launch_bounds__(256)
void attn_mma_kernel(const __half* __restrict__ qf,
                     const __half* __restrict__ kf,
                     const __half* __restrict__ vf,
                     __half* __restrict__ of)
{
    extern __shared__ char dsm[];
    const uint32_t sb = smem_u32(dsm);
    const int tid  = threadIdx.x;
    const int lane = tid & 31, w = tid >> 5;
    const int qt = (NS/128 - 1) - blockIdx.x;   // heavy tiles first
    const int h  = blockIdx.y;
    const int b  = blockIdx.z;
    const int q0 = qt * 128;
    const long long gbase = (long long)b * NS * ND + h * HD;

    // ---- stage Q (128 rows) into stage-0 region; consumed to regs ----
    {
        int r = tid & 127;
        const __half* src = qf + gbase + (long long)(q0 + r) * ND + (tid >> 7) * 64;
        uint32_t dst = sb + r * AT_RS + (tid >> 7) * 128;
#pragma unroll
        for (int c = 0; c < 8; c++) CP_ASYNC16(dst + c*16, src + c*8);
        CP_COMMIT();
        CP_WAIT0();
        __syncthreads();
    }

    // ---- Q fragments to registers (8 k16-chunks) ----
    uint32_t qfr[8][4];
    {
        uint32_t qaddr = sb + (w*16 + (lane & 15)) * AT_RS + (lane >> 4) * 16;
#pragma unroll
        for (int kc = 0; kc < 8; kc++)
            LDSM4(qfr[kc], qaddr + kc*32);
    }
    __syncthreads();   // done reading Q staging region

    // ---- K/V tile loader: 2 matrices x 64 rows, threads 0..127 ----
    const __half* kvsrc = nullptr;
    uint32_t kvdst = 0;
    const bool loader = (tid < 128);
    if (loader) {
        kvsrc = ((tid < 64) ? kf : vf) + gbase + (long long)(tid & 63) * ND;
        kvdst = sb + (tid >> 6) * AT_TSIZE + (tid & 63) * AT_RS;
    }

#define AT_ISSUE(jt, st) do { \
        if (loader) { \
            const __half* g = kvsrc + (long long)(jt) * 64 * ND; \
            uint32_t d = kvdst + (st) * AT_STAGE; \
            _Pragma("unroll") \
            for (int c = 0; c < 16; c++) CP_ASYNC16(d + c*16, g + c*8); \
        } \
        CP_COMMIT(); \
    } while (0)

    const int njt = 2*qt + 2;
    AT_ISSUE(0, 0);
    AT_ISSUE(1, 1);

    float m0v = -1e30f, m1v = -1e30f, l0 = 0.0f, l1 = 0.0f;
    float od[16][4];
#pragma unroll
    for (int nd = 0; nd < 16; nd++)
#pragma unroll
        for (int c = 0; c < 4; c++) od[nd][c] = 0.0f;

    for (int jt = 0; jt < njt; jt++) {
        const int st = jt & 1;
        CP_WAIT1();
        __syncthreads();
        const uint32_t kbase = sb + st * AT_STAGE;
        const uint32_t vbase = kbase + AT_TSIZE;

        // ---- S = Q·K^T (16 x 64 per warp), 1 pass ----
        float sc[8][4];
#pragma unroll
        for (int n = 0; n < 8; n++)
#pragma unroll
            for (int c = 0; c < 4; c++) sc[n][c] = 0.0f;

#pragma unroll
        for (int kc = 0; kc < 8; kc++) {
#pragma unroll
            for (int ng = 0; ng < 4; ng++) {
                uint32_t rk[4];
                LDSM4(rk, kbase + (ng*16 + (lane & 15)) * AT_RS
                          + kc*32 + (lane >> 4) * 16);
                uint32_t b0[2] = {rk[0], rk[2]}, b1[2] = {rk[1], rk[3]};
                MMA16816H(sc[2*ng],   qfr[kc], b0);
                MMA16816H(sc[2*ng+1], qfr[kc], b1);
            }
        }

        // ---- causal mask (only the two diagonal k-tiles) ----
        if (jt >= njt - 2) {
            const int qrow = q0 + w*16 + (lane >> 2);
            const int kc0  = jt*64 + (lane & 3)*2;
#pragma unroll
            for (int n = 0; n < 8; n++) {
                int kcol = kc0 + n*8;
                if (kcol     > qrow)     sc[n][0] = -1e30f;
                if (kcol + 1 > qrow)     sc[n][1] = -1e30f;
                if (kcol     > qrow + 8) sc[n][2] = -1e30f;
                if (kcol + 1 > qrow + 8) sc[n][3] = -1e30f;
            }
        }

        // ---- online softmax ----
        float mx0 = -1e30f, mx1 = -1e30f;
#pragma unroll
        for (int n = 0; n < 8; n++) {
            mx0 = fmaxf(mx0, fmaxf(sc[n][0], sc[n][1]));
            mx1 = fmaxf(mx1, fmaxf(sc[n][2], sc[n][3]));
        }
        mx0 = fmaxf(mx0, __shfl_xor_sync(0xffffffffu, mx0, 1));
        mx0 = fmaxf(mx0, __shfl_xor_sync(0xffffffffu, mx0, 2));
        mx1 = fmaxf(mx1, __shfl_xor_sync(0xffffffffu, mx1, 1));
        mx1 = fmaxf(mx1, __shfl_xor_sync(0xffffffffu, mx1, 2));
        float mn0 = fmaxf(m0v, mx0), mn1 = fmaxf(m1v, mx1);
        float corr0 = __expf(m0v - mn0), corr1 = __expf(m1v - mn1);
        float ps0 = 0.0f, ps1 = 0.0f;
#pragma unroll
        for (int n = 0; n < 8; n++) {
            sc[n][0] = __expf(sc[n][0] - mn0);
            sc[n][1] = __expf(sc[n][1] - mn0);
            sc[n][2] = __expf(sc[n][2] - mn1);
            sc[n][3] = __expf(sc[n][3] - mn1);
            ps0 += sc[n][0] + sc[n][1];
            ps1 += sc[n][2] + sc[n][3];
        }
        ps0 += __shfl_xor_sync(0xffffffffu, ps0, 1);
        ps0 += __shfl_xor_sync(0xffffffffu, ps0, 2);
        ps1 += __shfl_xor_sync(0xffffffffu, ps1, 1);
        ps1 += __shfl_xor_sync(0xffffffffu, ps1, 2);
        l0 = l0 * corr0 + ps0;  m0v = mn0;
        l1 = l1 * corr1 + ps1;  m1v = mn1;
#pragma unroll
        for (int nd = 0; nd < 16; nd++) {
            od[nd][0] *= corr0; od[nd][1] *= corr0;
            od[nd][2] *= corr1; od[nd][3] *= corr1;
        }

        // ---- repack P (C-frags) into single-fp16 A-frags ----
        uint32_t pa[4][4];
#pragma unroll
        for (int kc2 = 0; kc2 < 4; kc2++) {
            const int n0i = 2*kc2, n1i = 2*kc2 + 1;
            pa[kc2][0] = f16x2_pack(sc[n0i][0], sc[n0i][1]);
            pa[kc2][1] = f16x2_pack(sc[n0i][2], sc[n0i][3]);
            pa[kc2][2] = f16x2_pack(sc[n1i][0], sc[n1i][1]);
            pa[kc2][3] = f16x2_pack(sc[n1i][2], sc[n1i][3]);
        }

        // ---- O += P·V, 1 pass ----
#pragma unroll
        for (int d0 = 0; d0 < 8; d0++) {
#pragma unroll
            for (int kc2 = 0; kc2 < 4; kc2++) {
                uint32_t rv[4];
                LDSM4T(rv, vbase + (kc2*16 + (lane & 15)) * AT_RS
                           + d0*32 + (lane >> 4) * 16);
                uint32_t b0[2] = {rv[0], rv[1]}, b1[2] = {rv[2], rv[3]};
                MMA16816H(od[2*d0],   pa[kc2], b0);
                MMA16816H(od[2*d0+1], pa[kc2], b1);
            }
        }

        __syncthreads();
        if (jt + 2 < njt) AT_ISSUE(jt + 2, st);
        else CP_COMMIT();          // keep group-count invariant for WAIT1
    }

    // ---- epilogue: O / l -> fp16 ----
    const float i0 = 1.0f / l0, i1 = 1.0f / l1;
    const long long row0 = (long long)(b*NS + q0 + w*16 + (lane >> 2)) * ND + h * HD;
    const long long row1 = row0 + 8ll * ND;
#pragma unroll
    for (int nd = 0; nd < 16; nd++) {
        const int d = nd*8 + (lane & 3)*2;
        *(uint32_t*)&of[row0 + d] = f16x2_pack(od[nd][0]*i0, od[nd][1]*i0);
        *(uint32_t*)&of[row1 + d] = f16x2_pack(od[nd][2]*i1, od[nd][3]*i1);
    }
#undef AT_ISSUE
}

// ============================================================================
extern "C" void kernel_launch(void* const* d_in, const int* in_sizes, int n_in,
                              void* d_out, int out_size)
{
    (void)in_sizes; (void)n_in; (void)out_size;
    const float* queries = (const float*)d_in[0];
    const float* keys    = (const float*)d_in[1];
    const float* values  = (const float*)d_in[2];
    const float* Wq = (const float*)d_in[3];
    const float* bq = (const float*)d_in[4];
    const float* Wk = (const float*)d_in[5];
    const float* bk = (const float*)d_in[6];
    const float* Wv = (const float*)d_in[7];
    const float* bv = (const float*)d_in[8];
    const float* Wo = (const float*)d_in[9];
    const float* bo = (const float*)d_in[10];
    float* out = (float*)d_out;

    float *q, *k;
    __half *whf, *af, *of, *qf, *kf, *vf;
    cudaGetSymbolAddress((void**)&q,   g_q);
    cudaGetSymbolAddress((void**)&k,   g_k);
    cudaGetSymbolAddress((void**)&whf, g_whf);
    cudaGetSymbolAddress((void**)&af,  g_af);
    cudaGetSymbolAddress((void**)&of,  g_of);
    cudaGetSymbolAddress((void**)&qf,  g_qf);
    cudaGetSymbolAddress((void**)&kf,  g_kf);
    cudaGetSymbolAddress((void**)&vf,  g_vf);

    cudaFuncSetAttribute(gemm_qkv_kernel,
                         cudaFuncAttributeMaxDynamicSharedMemorySize, GF_SMEM);
    cudaFuncSetAttribute(gemm_f16_kernel,
                         cudaFuncAttributeMaxDynamicSharedMemorySize, GF_SMEM);
    cudaFuncSetAttribute(attn_mma_kernel,
                         cudaFuncAttributeMaxDynamicSharedMemorySize, AT_SMEM);

    // ---- weight transpose+convert (one launch, z=4) ----
    dim3 gw(ND/32, ND/32, 4), bw(32, 8);
    conv_w_all_kernel<<<gw, bw>>>(Wq, Wk, Wv, Wo, whf);

    // ---- activation convert (one launch, z=3) ----
    const int nconv = NM*ND/8/256;
    conv_a_all_kernel<<<dim3(nconv, 1, 3), 256>>>(queries, keys, values, af);

    // ---- Q/K/V projections (one launch, z=3) ----
    dim3 gqkv(ND/128, NM/128, 3);              // (16, 32, 3) = 1536 CTAs
    gemm_qkv_kernel<<<gqkv, 256, GF_SMEM>>>(af, whf, bq, bk, bv, q, k, vf);

    // ---- RoPE (one launch, z=2) ----
    int nrope = NM * NH * 64;
    rope_all_kernel<<<dim3(nrope/256, 1, 2), 256>>>(q, k, qf, kf);

    // ---- attention (fully 1-pass fp16) ----
    dim3 ga(NS/128, NH, NB);
    attn_mma_kernel<<<ga, 256, AT_SMEM>>>(qf, kf, vf, of);

    // ---- output projection ----
    dim3 gtg(ND/128, NM/128);                  // (16, 32)
    gemm_f16_kernel<<<gtg, 256, GF_SMEM>>>(of, whf + 3ll*ND*ND, bo, out, nullptr);
}